// round 1
// baseline (speedup 1.0000x reference)
#include <cuda_runtime.h>
#include <mma.h>
#include <math.h>

using namespace nvcuda;

#define HD   1024
#define LD   2048
#define BATCH 4
#define M_TOTAL 8192

// ---------------- scratch (no allocations allowed) ----------------
__device__ __align__(16) float g_delta_raw[(size_t)M_TOTAL * HD];
__device__ __align__(16) float g_residual [(size_t)M_TOTAL * HD];
__device__ __align__(16) float g_delta    [(size_t)M_TOTAL * HD];
__device__ float g_uC  [BATCH * HD];
__device__ float g_Csum[BATCH * HD];
__device__ float g_s   [BATCH * HD];   // per-batch column sums of x

// ---------------- small kernels ----------------
__global__ void __launch_bounds__(256) zero_kernel() {
    int i = blockIdx.x * 256 + threadIdx.x;
    if (i < BATCH * HD) { g_uC[i] = 0.f; g_s[i] = 0.f; }
}

// g_s[b, h] = sum_l x[b, l, h]  (split over L with atomics)
__global__ void __launch_bounds__(128) colsum_kernel(const float* __restrict__ x) {
    int h  = blockIdx.x * 128 + threadIdx.x;
    int b  = blockIdx.y;
    int l0 = blockIdx.z * 128;
    const float* p = x + ((size_t)b * LD + l0) * HD + h;
    float s = 0.f;
    #pragma unroll 8
    for (int l = 0; l < 128; l++) s += p[(size_t)l * HD];
    atomicAdd(&g_s[b * HD + h], s);
}

// g_Csum[b, h] = <W_proj[2048+h, :], g_s[b, :]>   (exact fp32 path)
__global__ void __launch_bounds__(256) csum_kernel(const float* __restrict__ Wp) {
    int gw   = blockIdx.x * 8 + (threadIdx.x >> 5);   // 4096 warps total
    int lane = threadIdx.x & 31;
    int b = gw >> 10;
    int h = gw & (HD - 1);
    const float* w = Wp + (size_t)(2 * HD + h) * HD;
    const float* s = g_s + b * HD;
    float acc = 0.f;
    for (int k = lane; k < HD; k += 32) acc += w[k] * s[k];
    #pragma unroll
    for (int off = 16; off; off >>= 1) acc += __shfl_down_sync(0xffffffffu, acc, off);
    if (lane == 0) g_Csum[gw] = acc;
}

// ---------------- tf32 WMMA GEMMs ----------------
// Block tile 128x128, K-chunk 32, 8 warps (2x4), warp tile 64x32.
constexpr int BM = 128, BN = 128, KC = 32, LDS = 36;

// GEMM1: out[m, n] = sum_k x[m,k] * W_proj[wrow(n), k], n in [0, 3072)
//   n <  1024 -> delta_raw (W rows n)
//   n in [1024,2048) -> Cs (W rows n+1024): fused uC reduction, not stored
//   n >= 2048 -> residual (W rows n+1024)
__global__ void __launch_bounds__(256) gemm1_kernel(const float* __restrict__ x,
                                                    const float* __restrict__ Wp) {
    __shared__ float smem[9216];            // As(128*36) + Bs(128*36); epi(64*128) aliases
    float* As  = smem;
    float* Bs  = smem + BM * LDS;
    float* epi = smem;

    const int tid  = threadIdx.x;
    const int warp = tid >> 5;
    const int wm   = warp >> 2;
    const int wn   = warp & 3;
    const int m0   = blockIdx.y * BM;
    const int n0   = blockIdx.x * BN;
    const int wrow0 = (n0 < 1024) ? n0 : n0 + 1024;

    wmma::fragment<wmma::accumulator, 16, 16, 8, float> acc[4][2];
    #pragma unroll
    for (int i = 0; i < 4; i++)
        #pragma unroll
        for (int j = 0; j < 2; j++) wmma::fill_fragment(acc[i][j], 0.f);

    for (int k0 = 0; k0 < HD; k0 += KC) {
        __syncthreads();
        #pragma unroll
        for (int it = 0; it < 4; it++) {
            int idx = tid + it * 256;
            int row = idx >> 3;
            int c4  = (idx & 7) << 2;
            float4 v = *reinterpret_cast<const float4*>(x + (size_t)(m0 + row) * HD + k0 + c4);
            float* d = As + row * LDS + c4;
            d[0] = wmma::__float_to_tf32(v.x); d[1] = wmma::__float_to_tf32(v.y);
            d[2] = wmma::__float_to_tf32(v.z); d[3] = wmma::__float_to_tf32(v.w);
        }
        #pragma unroll
        for (int it = 0; it < 4; it++) {
            int idx = tid + it * 256;
            int row = idx >> 3;
            int c4  = (idx & 7) << 2;
            float4 v = *reinterpret_cast<const float4*>(Wp + (size_t)(wrow0 + row) * HD + k0 + c4);
            float* d = Bs + row * LDS + c4;
            d[0] = wmma::__float_to_tf32(v.x); d[1] = wmma::__float_to_tf32(v.y);
            d[2] = wmma::__float_to_tf32(v.z); d[3] = wmma::__float_to_tf32(v.w);
        }
        __syncthreads();
        #pragma unroll
        for (int ks = 0; ks < KC; ks += 8) {
            wmma::fragment<wmma::matrix_a, 16, 16, 8, wmma::precision::tf32, wmma::row_major> af[4];
            wmma::fragment<wmma::matrix_b, 16, 16, 8, wmma::precision::tf32, wmma::col_major> bf[2];
            #pragma unroll
            for (int i = 0; i < 4; i++)
                wmma::load_matrix_sync(af[i], As + (wm * 64 + i * 16) * LDS + ks, LDS);
            #pragma unroll
            for (int j = 0; j < 2; j++)
                wmma::load_matrix_sync(bf[j], Bs + (wn * 32 + j * 16) * LDS + ks, LDS);
            #pragma unroll
            for (int i = 0; i < 4; i++)
                #pragma unroll
                for (int j = 0; j < 2; j++)
                    wmma::mma_sync(acc[i][j], af[i], bf[j], acc[i][j]);
        }
    }

    float su = 0.f;   // uC partial (only tid < 128 in Cs region)
    #pragma unroll
    for (int half = 0; half < 2; half++) {
        __syncthreads();
        if (wm == half) {
            #pragma unroll
            for (int i = 0; i < 4; i++)
                #pragma unroll
                for (int j = 0; j < 2; j++)
                    wmma::store_matrix_sync(epi + (i * 16) * BN + wn * 32 + j * 16,
                                            acc[i][j], BN, wmma::mem_row_major);
        }
        __syncthreads();
        const int mbase = m0 + half * 64;
        if (n0 < 1024) {
            float* dst = g_delta_raw + (size_t)mbase * HD + n0;
            #pragma unroll
            for (int it = 0; it < 8; it++) {
                int idx = tid + it * 256;          // 64*32 float4
                int r = idx >> 5;
                int c4 = (idx & 31) << 2;
                *reinterpret_cast<float4*>(dst + (size_t)r * HD + c4) =
                    *reinterpret_cast<const float4*>(epi + r * BN + c4);
            }
        } else if (n0 < 2048) {
            if (tid < 128) {
                int hcol = (n0 - 1024) + tid;
                #pragma unroll 4
                for (int r = 0; r < 64; r++)
                    su += epi[r * BN + tid] * x[(size_t)(mbase + r) * HD + hcol];
            }
        } else {
            float* dst = g_residual + (size_t)mbase * HD + (n0 - 2048);
            #pragma unroll
            for (int it = 0; it < 8; it++) {
                int idx = tid + it * 256;
                int r = idx >> 5;
                int c4 = (idx & 31) << 2;
                *reinterpret_cast<float4*>(dst + (size_t)r * HD + c4) =
                    *reinterpret_cast<const float4*>(epi + r * BN + c4);
            }
        }
    }
    if (n0 >= 1024 && n0 < 2048 && tid < 128) {
        int b = m0 >> 11;
        atomicAdd(&g_uC[b * HD + (n0 - 1024) + tid], su);
    }
}

// GEMM2: g_delta = softplus(delta_raw @ W_delta^T + b_delta)
__global__ void __launch_bounds__(256) gemm2_kernel(const float* __restrict__ Wd,
                                                    const float* __restrict__ bd) {
    __shared__ float smem[9216];
    float* As  = smem;
    float* Bs  = smem + BM * LDS;
    float* epi = smem;
    const float* Ain = g_delta_raw;

    const int tid  = threadIdx.x;
    const int warp = tid >> 5;
    const int wm   = warp >> 2;
    const int wn   = warp & 3;
    const int m0   = blockIdx.y * BM;
    const int n0   = blockIdx.x * BN;

    wmma::fragment<wmma::accumulator, 16, 16, 8, float> acc[4][2];
    #pragma unroll
    for (int i = 0; i < 4; i++)
        #pragma unroll
        for (int j = 0; j < 2; j++) wmma::fill_fragment(acc[i][j], 0.f);

    for (int k0 = 0; k0 < HD; k0 += KC) {
        __syncthreads();
        #pragma unroll
        for (int it = 0; it < 4; it++) {
            int idx = tid + it * 256;
            int row = idx >> 3;
            int c4  = (idx & 7) << 2;
            float4 v = *reinterpret_cast<const float4*>(Ain + (size_t)(m0 + row) * HD + k0 + c4);
            float* d = As + row * LDS + c4;
            d[0] = wmma::__float_to_tf32(v.x); d[1] = wmma::__float_to_tf32(v.y);
            d[2] = wmma::__float_to_tf32(v.z); d[3] = wmma::__float_to_tf32(v.w);
        }
        #pragma unroll
        for (int it = 0; it < 4; it++) {
            int idx = tid + it * 256;
            int row = idx >> 3;
            int c4  = (idx & 7) << 2;
            float4 v = *reinterpret_cast<const float4*>(Wd + (size_t)(n0 + row) * HD + k0 + c4);
            float* d = Bs + row * LDS + c4;
            d[0] = wmma::__float_to_tf32(v.x); d[1] = wmma::__float_to_tf32(v.y);
            d[2] = wmma::__float_to_tf32(v.z); d[3] = wmma::__float_to_tf32(v.w);
        }
        __syncthreads();
        #pragma unroll
        for (int ks = 0; ks < KC; ks += 8) {
            wmma::fragment<wmma::matrix_a, 16, 16, 8, wmma::precision::tf32, wmma::row_major> af[4];
            wmma::fragment<wmma::matrix_b, 16, 16, 8, wmma::precision::tf32, wmma::col_major> bf[2];
            #pragma unroll
            for (int i = 0; i < 4; i++)
                wmma::load_matrix_sync(af[i], As + (wm * 64 + i * 16) * LDS + ks, LDS);
            #pragma unroll
            for (int j = 0; j < 2; j++)
                wmma::load_matrix_sync(bf[j], Bs + (wn * 32 + j * 16) * LDS + ks, LDS);
            #pragma unroll
            for (int i = 0; i < 4; i++)
                #pragma unroll
                for (int j = 0; j < 2; j++)
                    wmma::mma_sync(acc[i][j], af[i], bf[j], acc[i][j]);
        }
    }

    #pragma unroll
    for (int half = 0; half < 2; half++) {
        __syncthreads();
        if (wm == half) {
            #pragma unroll
            for (int i = 0; i < 4; i++)
                #pragma unroll
                for (int j = 0; j < 2; j++)
                    wmma::store_matrix_sync(epi + (i * 16) * BN + wn * 32 + j * 16,
                                            acc[i][j], BN, wmma::mem_row_major);
        }
        __syncthreads();
        const int mbase = m0 + half * 64;
        for (int idx = tid; idx < 64 * 128; idx += 256) {
            int r = idx >> 7;
            int c = idx & 127;
            float v = epi[idx] + bd[n0 + c];
            v = (v > 20.f) ? v : log1pf(expf(v));
            g_delta[(size_t)(mbase + r) * HD + n0 + c] = v;
        }
    }
}

// ---------------- fused cumsum + combine ----------------
// block (32,32): warp ty owns column h0+ty, lanes = 32 consecutive l's per tile.
__global__ void __launch_bounds__(1024) final_kernel(const float* __restrict__ Aa,
                                                     const float* __restrict__ Bp,
                                                     const float* __restrict__ Dp,
                                                     float* __restrict__ out) {
    __shared__ float sd[32][33];
    __shared__ float sr[32][33];
    __shared__ float sy[32][33];
    const int tx = threadIdx.x, ty = threadIdx.y;
    const int h0 = blockIdx.x * 32;
    const int b  = blockIdx.y;
    const int w    = ty;   // warp index == ty (blockDim.x == 32)
    const int lane = tx;
    const float A1  = Aa[h0 + w];
    const float B1  = Bp[h0 + w];
    const float Dv  = Dp[0];
    const float uCv = g_uC  [b * HD + h0 + w];
    const float Cv  = g_Csum[b * HD + h0 + w];
    const size_t base = (size_t)b * LD * HD;
    float carry = 0.f;

    for (int lt = 0; lt < LD; lt += 32) {
        size_t off = base + (size_t)(lt + ty) * HD + h0 + tx;
        sd[ty][tx] = g_delta[off];
        sr[ty][tx] = g_residual[off];
        __syncthreads();
        float dv = sd[lane][w];
        float v  = dv * B1;
        #pragma unroll
        for (int o = 1; o < 32; o <<= 1) {
            float nb = __shfl_up_sync(0xffffffffu, v, o);
            if (lane >= o) v += nb;
        }
        float dB = carry + v;
        carry += __shfl_sync(0xffffffffu, v, 31);
        float dA = expf(dv * A1) * B1;
        sy[lane][w] = dA * uCv + dB * Cv + sr[lane][w] * Dv;
        __syncthreads();
        out[off] = sy[ty][tx];
    }
}

// ---------------- launch ----------------
extern "C" void kernel_launch(void* const* d_in, const int* in_sizes, int n_in,
                              void* d_out, int out_size) {
    (void)in_sizes; (void)n_in; (void)out_size;
    const float* x  = (const float*)d_in[0];
    const float* Wp = (const float*)d_in[1];
    const float* A  = (const float*)d_in[2];
    const float* Bp = (const float*)d_in[3];
    const float* D  = (const float*)d_in[4];
    const float* Wd = (const float*)d_in[5];
    const float* bd = (const float*)d_in[6];
    float* out = (float*)d_out;

    zero_kernel<<<16, 256>>>();
    colsum_kernel<<<dim3(HD / 128, BATCH, LD / 128), 128>>>(x);
    csum_kernel<<<512, 256>>>(Wp);
    gemm1_kernel<<<dim3(24, 64), 256>>>(x, Wp);
    gemm2_kernel<<<dim3(8, 64), 256>>>(Wd, bd);
    final_kernel<<<dim3(HD / 32, BATCH), dim3(32, 32)>>>(A, Bp, D, out);
}

// round 4
// speedup vs baseline: 3.1258x; 3.1258x over previous
#include <cuda_runtime.h>
#include <cuda_bf16.h>
#include <cstdint>
#include <math.h>

#define HD   1024
#define LD   2048
#define BATCH 4
#define M_TOTAL 8192

// ---------------- scratch (no allocations allowed) ----------------
__device__ __align__(16) __nv_bfloat16 g_xb [(size_t)M_TOTAL * HD];
__device__ __align__(16) __nv_bfloat16 g_Wpb[(size_t)3072 * HD];
__device__ __align__(16) __nv_bfloat16 g_Wdb[(size_t)HD * HD];
__device__ __align__(16) __nv_bfloat16 g_drb[(size_t)M_TOTAL * HD];
__device__ __align__(16) float g_residual[(size_t)M_TOTAL * HD];
__device__ __align__(16) float g_delta   [(size_t)M_TOTAL * HD];
__device__ float g_uC  [BATCH * HD];
__device__ float g_Csum[BATCH * HD];
__device__ float g_s   [BATCH * HD];

// ---------------- helpers ----------------
__device__ __forceinline__ uint32_t smem_u32(const void* p) {
    uint32_t a;
    asm("{ .reg .u64 t; cvta.to.shared.u64 t, %1; cvt.u32.u64 %0, t; }" : "=r"(a) : "l"(p));
    return a;
}
__device__ __forceinline__ void cp16(uint32_t s, const void* g) {
    asm volatile("cp.async.cg.shared.global [%0], [%1], 16;" :: "r"(s), "l"(g));
}
#define CP_COMMIT() asm volatile("cp.async.commit_group;" ::: "memory")
#define CP_WAIT2()  asm volatile("cp.async.wait_group 2;" ::: "memory")
#define CP_WAIT0()  asm volatile("cp.async.wait_group 0;" ::: "memory")

#define LDSM4(r, addr) \
    asm volatile("ldmatrix.sync.aligned.m8n8.x4.shared.b16 {%0,%1,%2,%3}, [%4];" \
        : "=r"((r)[0]), "=r"((r)[1]), "=r"((r)[2]), "=r"((r)[3]) : "r"(addr))

__device__ __forceinline__ void mma16816(float* c, const uint32_t* a, const uint32_t* b) {
    asm volatile(
        "mma.sync.aligned.m16n8k16.row.col.f32.bf16.bf16.f32 "
        "{%0,%1,%2,%3}, {%4,%5,%6,%7}, {%8,%9}, {%0,%1,%2,%3};"
        : "+f"(c[0]), "+f"(c[1]), "+f"(c[2]), "+f"(c[3])
        : "r"(a[0]), "r"(a[1]), "r"(a[2]), "r"(a[3]), "r"(b[0]), "r"(b[1]));
}
__device__ __forceinline__ uint32_t pack_bf2(float a, float b) {
    __nv_bfloat162 h = __floats2bfloat162_rn(a, b);
    return *reinterpret_cast<uint32_t*>(&h);
}

// ---------------- small kernels ----------------
__global__ void __launch_bounds__(256) zero_kernel() {
    int i = blockIdx.x * 256 + threadIdx.x;
    if (i < BATCH * HD) { g_uC[i] = 0.f; g_s[i] = 0.f; }
}

__global__ void __launch_bounds__(128) colsum_kernel(const float* __restrict__ x) {
    int h  = blockIdx.x * 128 + threadIdx.x;
    int b  = blockIdx.y;
    int l0 = blockIdx.z * 128;
    const float* p = x + ((size_t)b * LD + l0) * HD + h;
    float s = 0.f;
    #pragma unroll 8
    for (int l = 0; l < 128; l++) s += p[(size_t)l * HD];
    atomicAdd(&g_s[b * HD + h], s);
}

// exact fp32 path for Csum (error-critical: multiplied by dB ~ O(20))
__global__ void __launch_bounds__(256) csum_kernel(const float* __restrict__ Wp) {
    int gw   = blockIdx.x * 8 + (threadIdx.x >> 5);
    int lane = threadIdx.x & 31;
    int b = gw >> 10;
    int h = gw & (HD - 1);
    const float* w = Wp + (size_t)(2 * HD + h) * HD;
    const float* s = g_s + b * HD;
    float acc = 0.f;
    for (int k = lane; k < HD; k += 32) acc += w[k] * s[k];
    #pragma unroll
    for (int off = 16; off; off >>= 1) acc += __shfl_down_sync(0xffffffffu, acc, off);
    if (lane == 0) g_Csum[gw] = acc;
}

// ---------------- fp32 -> bf16 conversions ----------------
__global__ void __launch_bounds__(256) conv_x_kernel(const float* __restrict__ in) {
    size_t i = ((size_t)blockIdx.x * 256 + threadIdx.x) * 8;
    float4 a = *reinterpret_cast<const float4*>(in + i);
    float4 b = *reinterpret_cast<const float4*>(in + i + 4);
    uint4 o;
    o.x = pack_bf2(a.x, a.y); o.y = pack_bf2(a.z, a.w);
    o.z = pack_bf2(b.x, b.y); o.w = pack_bf2(b.z, b.w);
    *reinterpret_cast<uint4*>(g_xb + i) = o;
}
// W_proj rows remapped: out rows [0,1024)=delta W, [1024,2048)=Cs W (src+1024), [2048,3072)=res W
__global__ void __launch_bounds__(256) conv_wp_kernel(const float* __restrict__ Wp) {
    int gid  = blockIdx.x * 256 + threadIdx.x;
    int orow = gid >> 7;
    int c    = (gid & 127) * 8;
    int srow = (orow < 1024) ? orow : orow + 1024;
    const float* in = Wp + (size_t)srow * HD + c;
    float4 a = *reinterpret_cast<const float4*>(in);
    float4 b = *reinterpret_cast<const float4*>(in + 4);
    uint4 o;
    o.x = pack_bf2(a.x, a.y); o.y = pack_bf2(a.z, a.w);
    o.z = pack_bf2(b.x, b.y); o.w = pack_bf2(b.z, b.w);
    *reinterpret_cast<uint4*>(g_Wpb + (size_t)orow * HD + c) = o;
}
__global__ void __launch_bounds__(256) conv_wd_kernel(const float* __restrict__ Wd) {
    size_t i = ((size_t)blockIdx.x * 256 + threadIdx.x) * 8;
    float4 a = *reinterpret_cast<const float4*>(Wd + i);
    float4 b = *reinterpret_cast<const float4*>(Wd + i + 4);
    uint4 o;
    o.x = pack_bf2(a.x, a.y); o.y = pack_bf2(a.z, a.w);
    o.z = pack_bf2(b.x, b.y); o.w = pack_bf2(b.z, b.w);
    *reinterpret_cast<uint4*>(g_Wdb + i) = o;
}

// ---------------- bf16 mma.sync GEMM, 4-stage cp.async pipeline ----------------
// Block 128x128, K-chunk 32 (2 k16 steps), 8 warps (2x4), warp tile 64x32.
// Stage: A 128x32 bf16 (8KB, swizzled) + B 128x32 bf16 (8KB). 4 stages = 64KB.
// smem: [0,512) uC partials; [1024, 1024+65536) stages.
constexpr int STAGE_BYTES = 16384;
constexpr int GEMM_SMEM   = 1024 + 4 * STAGE_BYTES;

__global__ void __launch_bounds__(256)
gemm_mma(const float* __restrict__ x, const float* __restrict__ bd, int mode) {
    extern __shared__ char smem[];
    float* suc = reinterpret_cast<float*>(smem);
    const uint32_t sdata = smem_u32(smem) + 1024;

    const int tid  = threadIdx.x;
    const int lane = tid & 31;
    const int warp = tid >> 5;
    const int wm   = warp >> 2;       // 0..1  (64-row half)
    const int wn   = warp & 3;        // 0..3  (32-col quarter)
    const int m0   = blockIdx.y * 128;
    const int n0   = blockIdx.x * 128;

    const __nv_bfloat16* Ab = mode ? g_drb : g_xb;
    const __nv_bfloat16* Bb = mode ? g_Wdb : g_Wpb;

    if (tid < 128) suc[tid] = 0.f;

    // per-thread cp.async source/dest mapping (2 segs of A + 2 of B per chunk)
    // seg: row = seg>>2, c16 = seg&3; swizzle: slot = c16 ^ ((row>>1)&3)
    // ldmatrix offsets (within a stage):
    uint32_t offA[2][4];   // [kstep][mi]
    #pragma unroll
    for (int ks = 0; ks < 2; ks++)
        #pragma unroll
        for (int mi = 0; mi < 4; mi++) {
            int row = wm * 64 + mi * 16 + (lane & 15);
            int c16 = ks * 2 + (lane >> 4);
            offA[ks][mi] = row * 64 + ((c16 ^ ((row >> 1) & 3)) << 4);
        }
    uint32_t offB[2][2];   // [kstep][npair]  (each covers 16 n-rows)
    #pragma unroll
    for (int ks = 0; ks < 2; ks++)
        #pragma unroll
        for (int np = 0; np < 2; np++) {
            int row = wn * 32 + np * 16 + (lane & 7) + ((lane & 16) >> 1);
            int c16 = ks * 2 + ((lane >> 3) & 1);
            offB[ks][np] = row * 64 + ((c16 ^ ((row >> 1) & 3)) << 4);
        }

    float acc[4][4][4];
    #pragma unroll
    for (int i = 0; i < 4; i++)
        #pragma unroll
        for (int j = 0; j < 4; j++)
            #pragma unroll
            for (int e = 0; e < 4; e++) acc[i][j][e] = 0.f;

    auto load_chunk = [&](int c) {
        const uint32_t sA = sdata + (c & 3) * STAGE_BYTES;
        const uint32_t sB = sA + 8192;
        const __nv_bfloat16* gA = Ab + (size_t)m0 * HD + c * 32;
        const __nv_bfloat16* gB = Bb + (size_t)n0 * HD + c * 32;
        #pragma unroll
        for (int it = 0; it < 2; it++) {
            int seg = tid + it * 256;
            int row = seg >> 2;
            int c16 = seg & 3;
            uint32_t off = row * 64 + ((c16 ^ ((row >> 1) & 3)) << 4);
            cp16(sA + off, gA + (size_t)row * HD + c16 * 8);
            cp16(sB + off, gB + (size_t)row * HD + c16 * 8);
        }
        CP_COMMIT();
    };

    load_chunk(0); load_chunk(1); load_chunk(2);

    #pragma unroll 1
    for (int k = 0; k < 32; k++) {
        if (k <= 28) { CP_WAIT2(); } else { CP_WAIT0(); }
        __syncthreads();
        if (k <= 28) load_chunk(k + 3);

        const uint32_t sA = sdata + (k & 3) * STAGE_BYTES;
        const uint32_t sB = sA + 8192;
        #pragma unroll
        for (int ks = 0; ks < 2; ks++) {
            uint32_t a[4][4], b[4][2];
            #pragma unroll
            for (int mi = 0; mi < 4; mi++) LDSM4(a[mi], sA + offA[ks][mi]);
            #pragma unroll
            for (int np = 0; np < 2; np++) {
                uint32_t r[4];
                LDSM4(r, sB + offB[ks][np]);
                b[np*2+0][0] = r[0]; b[np*2+0][1] = r[1];
                b[np*2+1][0] = r[2]; b[np*2+1][1] = r[3];
            }
            #pragma unroll
            for (int mi = 0; mi < 4; mi++)
                #pragma unroll
                for (int nj = 0; nj < 4; nj++)
                    mma16816(acc[mi][nj], a[mi], b[nj]);
        }
    }

    // -------- epilogue (register-direct) --------
    const int mrow = m0 + wm * 64 + (lane >> 2);
    const int cloc = wn * 32 + (lane & 3) * 2;

    if (mode == 0) {
        if (n0 < 1024) {                        // delta_raw -> bf16
            #pragma unroll
            for (int mi = 0; mi < 4; mi++)
                #pragma unroll
                for (int nj = 0; nj < 4; nj++) {
                    int r = mrow + mi * 16;
                    int c = n0 + cloc + nj * 8;
                    *reinterpret_cast<uint32_t*>(g_drb + (size_t)r * HD + c) =
                        pack_bf2(acc[mi][nj][0], acc[mi][nj][1]);
                    *reinterpret_cast<uint32_t*>(g_drb + (size_t)(r + 8) * HD + c) =
                        pack_bf2(acc[mi][nj][2], acc[mi][nj][3]);
                }
        } else if (n0 < 2048) {                 // Cs: fused uC reduction
            const int h0 = n0 - 1024;
            float cs[8];
            #pragma unroll
            for (int e = 0; e < 8; e++) cs[e] = 0.f;
            #pragma unroll
            for (int mi = 0; mi < 4; mi++)
                #pragma unroll
                for (int half = 0; half < 2; half++) {
                    int r = mrow + mi * 16 + half * 8;
                    const float* xr = x + (size_t)r * HD + h0 + cloc;
                    #pragma unroll
                    for (int nj = 0; nj < 4; nj++) {
                        float2 xv = *reinterpret_cast<const float2*>(xr + nj * 8);
                        cs[nj*2+0] += acc[mi][nj][half*2+0] * xv.x;
                        cs[nj*2+1] += acc[mi][nj][half*2+1] * xv.y;
                    }
                }
            #pragma unroll
            for (int nj = 0; nj < 4; nj++) {
                atomicAdd(&suc[cloc + nj * 8],     cs[nj*2+0]);
                atomicAdd(&suc[cloc + nj * 8 + 1], cs[nj*2+1]);
            }
            __syncthreads();
            if (tid < 128)
                atomicAdd(&g_uC[(m0 >> 11) * HD + h0 + tid], suc[tid]);
        } else {                                // residual -> fp32
            const int cb = n0 - 2048;
            #pragma unroll
            for (int mi = 0; mi < 4; mi++)
                #pragma unroll
                for (int nj = 0; nj < 4; nj++) {
                    int r = mrow + mi * 16;
                    int c = cb + cloc + nj * 8;
                    *reinterpret_cast<float2*>(g_residual + (size_t)r * HD + c) =
                        make_float2(acc[mi][nj][0], acc[mi][nj][1]);
                    *reinterpret_cast<float2*>(g_residual + (size_t)(r + 8) * HD + c) =
                        make_float2(acc[mi][nj][2], acc[mi][nj][3]);
                }
        }
    } else {                                    // GEMM2: bias + softplus -> g_delta
        #pragma unroll
        for (int mi = 0; mi < 4; mi++)
            #pragma unroll
            for (int nj = 0; nj < 4; nj++) {
                int r = mrow + mi * 16;
                int c = n0 + cloc + nj * 8;
                float b0 = bd[c], b1 = bd[c + 1];
                float v0 = acc[mi][nj][0] + b0;
                float v1 = acc[mi][nj][1] + b1;
                float v2 = acc[mi][nj][2] + b0;
                float v3 = acc[mi][nj][3] + b1;
                v0 = (v0 > 20.f) ? v0 : log1pf(expf(v0));
                v1 = (v1 > 20.f) ? v1 : log1pf(expf(v1));
                v2 = (v2 > 20.f) ? v2 : log1pf(expf(v2));
                v3 = (v3 > 20.f) ? v3 : log1pf(expf(v3));
                *reinterpret_cast<float2*>(g_delta + (size_t)r * HD + c) = make_float2(v0, v1);
                *reinterpret_cast<float2*>(g_delta + (size_t)(r + 8) * HD + c) = make_float2(v2, v3);
            }
    }
}

// ---------------- fused cumsum + combine ----------------
__global__ void __launch_bounds__(1024) final_kernel(const float* __restrict__ Aa,
                                                     const float* __restrict__ Bp,
                                                     const float* __restrict__ Dp,
                                                     float* __restrict__ out) {
    __shared__ float sd[32][33];
    __shared__ float sr[32][33];
    __shared__ float sy[32][33];
    const int tx = threadIdx.x, ty = threadIdx.y;
    const int h0 = blockIdx.x * 32;
    const int b  = blockIdx.y;
    const int w    = ty;
    const int lane = tx;
    const float A1  = Aa[h0 + w];
    const float B1  = Bp[h0 + w];
    const float Dv  = Dp[0];
    const float uCv = g_uC  [b * HD + h0 + w];
    const float Cv  = g_Csum[b * HD + h0 + w];
    const size_t base = (size_t)b * LD * HD;
    float carry = 0.f;

    for (int lt = 0; lt < LD; lt += 32) {
        size_t off = base + (size_t)(lt + ty) * HD + h0 + tx;
        sd[ty][tx] = g_delta[off];
        sr[ty][tx] = g_residual[off];
        __syncthreads();
        float dv = sd[lane][w];
        float v  = dv * B1;
        #pragma unroll
        for (int o = 1; o < 32; o <<= 1) {
            float nb = __shfl_up_sync(0xffffffffu, v, o);
            if (lane >= o) v += nb;
        }
        float dB = carry + v;
        carry += __shfl_sync(0xffffffffu, v, 31);
        float dA = expf(dv * A1) * B1;
        sy[lane][w] = dA * uCv + dB * Cv + sr[lane][w] * Dv;
        __syncthreads();
        out[off] = sy[ty][tx];
    }
}

// ---------------- launch ----------------
extern "C" void kernel_launch(void* const* d_in, const int* in_sizes, int n_in,
                              void* d_out, int out_size) {
    (void)in_sizes; (void)n_in; (void)out_size;
    const float* x  = (const float*)d_in[0];
    const float* Wp = (const float*)d_in[1];
    const float* A  = (const float*)d_in[2];
    const float* Bp = (const float*)d_in[3];
    const float* D  = (const float*)d_in[4];
    const float* Wd = (const float*)d_in[5];
    const float* bd = (const float*)d_in[6];
    float* out = (float*)d_out;

    cudaFuncSetAttribute(gemm_mma, cudaFuncAttributeMaxDynamicSharedMemorySize, GEMM_SMEM);

    zero_kernel<<<16, 256>>>();
    colsum_kernel<<<dim3(HD / 128, BATCH, LD / 128), 128>>>(x);
    csum_kernel<<<512, 256>>>(Wp);
    conv_x_kernel<<<4096, 256>>>(x);
    conv_wp_kernel<<<1536, 256>>>(Wp);
    conv_wd_kernel<<<512, 256>>>(Wd);
    gemm_mma<<<dim3(24, 64), 256, GEMM_SMEM>>>(x, bd, 0);
    gemm_mma<<<dim3(8, 64), 256, GEMM_SMEM>>>(x, bd, 1);
    final_kernel<<<dim3(HD / 32, BATCH), dim3(32, 32)>>>(A, Bp, D, out);
}

// round 5
// speedup vs baseline: 3.5797x; 1.1452x over previous
#include <cuda_runtime.h>
#include <cuda_bf16.h>
#include <cstdint>
#include <math.h>

#define HD   1024
#define LD   2048
#define BATCH 4
#define M_TOTAL 8192

// ---------------- scratch (no allocations allowed) ----------------
__device__ __align__(16) __nv_bfloat16 g_xb [(size_t)M_TOTAL * HD];
__device__ __align__(16) __nv_bfloat16 g_Wpb[(size_t)3072 * HD];  // [0,1024)=W_eff, [1024,2048)=W_C, [2048,3072)=W_res
__device__ __align__(16) __nv_bfloat16 g_W1T[(size_t)HD * HD];    // W1 transposed (for W_eff GEMM B operand)
__device__ __align__(16) __nv_bfloat16 g_Wdb[(size_t)HD * HD];
__device__ __align__(16) __nv_bfloat16 g_resb[(size_t)M_TOTAL * HD];
__device__ __align__(16) float g_delta[(size_t)M_TOTAL * HD];
__device__ float g_uC  [BATCH * HD];
__device__ float g_Csum[BATCH * HD];
__device__ float g_s   [BATCH * HD];

// ---------------- helpers ----------------
__device__ __forceinline__ uint32_t smem_u32(const void* p) {
    uint32_t a;
    asm("{ .reg .u64 t; cvta.to.shared.u64 t, %1; cvt.u32.u64 %0, t; }" : "=r"(a) : "l"(p));
    return a;
}
__device__ __forceinline__ void cp16(uint32_t s, const void* g) {
    asm volatile("cp.async.cg.shared.global [%0], [%1], 16;" :: "r"(s), "l"(g));
}
#define CP_COMMIT() asm volatile("cp.async.commit_group;" ::: "memory")
#define CP_WAIT2()  asm volatile("cp.async.wait_group 2;" ::: "memory")
#define CP_WAIT0()  asm volatile("cp.async.wait_group 0;" ::: "memory")

#define LDSM4(r, addr) \
    asm volatile("ldmatrix.sync.aligned.m8n8.x4.shared.b16 {%0,%1,%2,%3}, [%4];" \
        : "=r"((r)[0]), "=r"((r)[1]), "=r"((r)[2]), "=r"((r)[3]) : "r"(addr))

__device__ __forceinline__ void mma16816(float* c, const uint32_t* a, const uint32_t* b) {
    asm volatile(
        "mma.sync.aligned.m16n8k16.row.col.f32.bf16.bf16.f32 "
        "{%0,%1,%2,%3}, {%4,%5,%6,%7}, {%8,%9}, {%0,%1,%2,%3};"
        : "+f"(c[0]), "+f"(c[1]), "+f"(c[2]), "+f"(c[3])
        : "r"(a[0]), "r"(a[1]), "r"(a[2]), "r"(a[3]), "r"(b[0]), "r"(b[1]));
}
__device__ __forceinline__ uint32_t pack_bf2(float a, float b) {
    __nv_bfloat162 h = __floats2bfloat162_rn(a, b);
    return *reinterpret_cast<uint32_t*>(&h);
}

// ---------------- small kernels ----------------
__global__ void __launch_bounds__(256) zero_kernel() {
    int i = blockIdx.x * 256 + threadIdx.x;
    if (i < BATCH * HD) { g_uC[i] = 0.f; g_s[i] = 0.f; }
}

// fp32 column sums of x (exact path feeding Csum)
__global__ void __launch_bounds__(128) colsum_kernel(const float* __restrict__ x) {
    int h  = blockIdx.x * 128 + threadIdx.x;
    int b  = blockIdx.y;
    int l0 = blockIdx.z * 128;
    const float* p = x + ((size_t)b * LD + l0) * HD + h;
    float s = 0.f;
    #pragma unroll 8
    for (int l = 0; l < 128; l++) s += p[(size_t)l * HD];
    atomicAdd(&g_s[b * HD + h], s);
}

// exact fp32 Csum[b,h] = <W_proj[2048+h,:], g_s[b,:]> (error-critical)
__global__ void __launch_bounds__(256) csum_kernel(const float* __restrict__ Wp) {
    int gw   = blockIdx.x * 8 + (threadIdx.x >> 5);
    int lane = threadIdx.x & 31;
    int b = gw >> 10;
    int h = gw & (HD - 1);
    const float* w = Wp + (size_t)(2 * HD + h) * HD;
    const float* s = g_s + b * HD;
    float acc = 0.f;
    for (int k = lane; k < HD; k += 32) acc += w[k] * s[k];
    #pragma unroll
    for (int off = 16; off; off >>= 1) acc += __shfl_down_sync(0xffffffffu, acc, off);
    if (lane == 0) g_Csum[gw] = acc;
}

// ---------------- fp32 -> bf16 conversions ----------------
__global__ void __launch_bounds__(256) conv_x_kernel(const float* __restrict__ in) {
    size_t i = ((size_t)blockIdx.x * 256 + threadIdx.x) * 8;
    float4 a = *reinterpret_cast<const float4*>(in + i);
    float4 b = *reinterpret_cast<const float4*>(in + i + 4);
    uint4 o;
    o.x = pack_bf2(a.x, a.y); o.y = pack_bf2(a.z, a.w);
    o.z = pack_bf2(b.x, b.y); o.w = pack_bf2(b.z, b.w);
    *reinterpret_cast<uint4*>(g_xb + i) = o;
}
// W_proj rows 2048..4095 -> g_Wpb rows [1024,3072)  (W_C then W_res)
__global__ void __launch_bounds__(256) conv_wp_kernel(const float* __restrict__ Wp) {
    int gid  = blockIdx.x * 256 + threadIdx.x;          // 2048*128 threads
    int orow = 1024 + (gid >> 7);
    int c    = (gid & 127) * 8;
    const float* in = Wp + (size_t)(orow + 1024) * HD + c;
    float4 a = *reinterpret_cast<const float4*>(in);
    float4 b = *reinterpret_cast<const float4*>(in + 4);
    uint4 o;
    o.x = pack_bf2(a.x, a.y); o.y = pack_bf2(a.z, a.w);
    o.z = pack_bf2(b.x, b.y); o.w = pack_bf2(b.z, b.w);
    *reinterpret_cast<uint4*>(g_Wpb + (size_t)orow * HD + c) = o;
}
// W1 = W_proj rows [0,1024): transpose-convert -> g_W1T[n][j] = bf16(W1[j][n])
__global__ void __launch_bounds__(256) conv_w1t_kernel(const float* __restrict__ Wp) {
    __shared__ float tile[32][33];
    const int tx = threadIdx.x, ty = threadIdx.y;       // 32 x 8
    const int bx = blockIdx.x * 32, by = blockIdx.y * 32;
    #pragma unroll
    for (int p = 0; p < 4; p++)
        tile[ty + p * 8][tx] = Wp[(size_t)(by + ty + p * 8) * HD + bx + tx];
    __syncthreads();
    #pragma unroll
    for (int p = 0; p < 4; p++) {
        int r = ty + p * 8;
        g_W1T[(size_t)(bx + r) * HD + by + tx] = __float2bfloat16(tile[tx][r]);
    }
}
__global__ void __launch_bounds__(256) conv_wd_kernel(const float* __restrict__ Wd) {
    size_t i = ((size_t)blockIdx.x * 256 + threadIdx.x) * 8;
    float4 a = *reinterpret_cast<const float4*>(Wd + i);
    float4 b = *reinterpret_cast<const float4*>(Wd + i + 4);
    uint4 o;
    o.x = pack_bf2(a.x, a.y); o.y = pack_bf2(a.z, a.w);
    o.z = pack_bf2(b.x, b.y); o.w = pack_bf2(b.z, b.w);
    *reinterpret_cast<uint4*>(g_Wdb + i) = o;
}

// ---------------- bf16 mma.sync GEMM, 4-stage cp.async pipeline ----------------
// Block 128x128, K-chunk 32 (2 k16 steps), 8 warps (2x4), warp tile 64x32.
// mode 0: main GEMM  A=g_xb, B=g_Wpb; n0<1024: delta=softplus(.+bd) -> g_delta fp32
//                    n0 in [1024,2048): Cs -> fused uC; n0>=2048: residual -> g_resb bf16
// mode 1: W_eff GEMM A=g_Wdb, B=g_W1T; store bf16 -> g_Wpb rows [0,1024)
constexpr int STAGE_BYTES = 16384;
constexpr int GEMM_SMEM   = 1024 + 4 * STAGE_BYTES;

__global__ void __launch_bounds__(256)
gemm_mma(const float* __restrict__ x, const float* __restrict__ bd, int mode) {
    extern __shared__ char smem[];
    float* suc = reinterpret_cast<float*>(smem);
    const uint32_t sdata = smem_u32(smem) + 1024;

    const int tid  = threadIdx.x;
    const int lane = tid & 31;
    const int warp = tid >> 5;
    const int wm   = warp >> 2;
    const int wn   = warp & 3;
    const int m0   = blockIdx.y * 128;
    const int n0   = blockIdx.x * 128;

    const __nv_bfloat16* Ab = mode ? g_Wdb : g_xb;
    const __nv_bfloat16* Bb = mode ? g_W1T : g_Wpb;

    if (tid < 128) suc[tid] = 0.f;

    uint32_t offA[2][4];
    #pragma unroll
    for (int ks = 0; ks < 2; ks++)
        #pragma unroll
        for (int mi = 0; mi < 4; mi++) {
            int row = wm * 64 + mi * 16 + (lane & 15);
            int c16 = ks * 2 + (lane >> 4);
            offA[ks][mi] = row * 64 + ((c16 ^ ((row >> 1) & 3)) << 4);
        }
    uint32_t offB[2][2];
    #pragma unroll
    for (int ks = 0; ks < 2; ks++)
        #pragma unroll
        for (int np = 0; np < 2; np++) {
            int row = wn * 32 + np * 16 + (lane & 7) + ((lane & 16) >> 1);
            int c16 = ks * 2 + ((lane >> 3) & 1);
            offB[ks][np] = row * 64 + ((c16 ^ ((row >> 1) & 3)) << 4);
        }

    float acc[4][4][4];
    #pragma unroll
    for (int i = 0; i < 4; i++)
        #pragma unroll
        for (int j = 0; j < 4; j++)
            #pragma unroll
            for (int e = 0; e < 4; e++) acc[i][j][e] = 0.f;

    auto load_chunk = [&](int c) {
        const uint32_t sA = sdata + (c & 3) * STAGE_BYTES;
        const uint32_t sB = sA + 8192;
        const __nv_bfloat16* gA = Ab + (size_t)m0 * HD + c * 32;
        const __nv_bfloat16* gB = Bb + (size_t)n0 * HD + c * 32;
        #pragma unroll
        for (int it = 0; it < 2; it++) {
            int seg = tid + it * 256;
            int row = seg >> 2;
            int c16 = seg & 3;
            uint32_t off = row * 64 + ((c16 ^ ((row >> 1) & 3)) << 4);
            cp16(sA + off, gA + (size_t)row * HD + c16 * 8);
            cp16(sB + off, gB + (size_t)row * HD + c16 * 8);
        }
        CP_COMMIT();
    };

    load_chunk(0); load_chunk(1); load_chunk(2);

    #pragma unroll 1
    for (int k = 0; k < 32; k++) {
        if (k <= 28) { CP_WAIT2(); } else { CP_WAIT0(); }
        __syncthreads();
        if (k <= 28) load_chunk(k + 3);

        const uint32_t sA = sdata + (k & 3) * STAGE_BYTES;
        const uint32_t sB = sA + 8192;
        #pragma unroll
        for (int ks = 0; ks < 2; ks++) {
            uint32_t a[4][4], b[4][2];
            #pragma unroll
            for (int mi = 0; mi < 4; mi++) LDSM4(a[mi], sA + offA[ks][mi]);
            #pragma unroll
            for (int np = 0; np < 2; np++) {
                uint32_t r[4];
                LDSM4(r, sB + offB[ks][np]);
                b[np*2+0][0] = r[0]; b[np*2+0][1] = r[1];
                b[np*2+1][0] = r[2]; b[np*2+1][1] = r[3];
            }
            #pragma unroll
            for (int mi = 0; mi < 4; mi++)
                #pragma unroll
                for (int nj = 0; nj < 4; nj++)
                    mma16816(acc[mi][nj], a[mi], b[nj]);
        }
    }

    // -------- epilogue (register-direct) --------
    const int mrow = m0 + wm * 64 + (lane >> 2);
    const int cloc = wn * 32 + (lane & 3) * 2;

    if (mode == 1) {                            // W_eff -> bf16 g_Wpb[0,1024)
        #pragma unroll
        for (int mi = 0; mi < 4; mi++)
            #pragma unroll
            for (int nj = 0; nj < 4; nj++) {
                int r = mrow + mi * 16;
                int c = n0 + cloc + nj * 8;
                *reinterpret_cast<uint32_t*>(g_Wpb + (size_t)r * HD + c) =
                    pack_bf2(acc[mi][nj][0], acc[mi][nj][1]);
                *reinterpret_cast<uint32_t*>(g_Wpb + (size_t)(r + 8) * HD + c) =
                    pack_bf2(acc[mi][nj][2], acc[mi][nj][3]);
            }
    } else if (n0 < 1024) {                     // delta = softplus(. + bd) -> fp32
        #pragma unroll
        for (int mi = 0; mi < 4; mi++)
            #pragma unroll
            for (int nj = 0; nj < 4; nj++) {
                int r = mrow + mi * 16;
                int c = n0 + cloc + nj * 8;
                float b0 = bd[c], b1 = bd[c + 1];
                float v0 = acc[mi][nj][0] + b0;
                float v1 = acc[mi][nj][1] + b1;
                float v2 = acc[mi][nj][2] + b0;
                float v3 = acc[mi][nj][3] + b1;
                v0 = (v0 > 20.f) ? v0 : log1pf(expf(v0));
                v1 = (v1 > 20.f) ? v1 : log1pf(expf(v1));
                v2 = (v2 > 20.f) ? v2 : log1pf(expf(v2));
                v3 = (v3 > 20.f) ? v3 : log1pf(expf(v3));
                *reinterpret_cast<float2*>(g_delta + (size_t)r * HD + c) = make_float2(v0, v1);
                *reinterpret_cast<float2*>(g_delta + (size_t)(r + 8) * HD + c) = make_float2(v2, v3);
            }
    } else if (n0 < 2048) {                     // Cs: fused uC reduction
        const int h0 = n0 - 1024;
        float cs[8];
        #pragma unroll
        for (int e = 0; e < 8; e++) cs[e] = 0.f;
        #pragma unroll
        for (int mi = 0; mi < 4; mi++)
            #pragma unroll
            for (int half = 0; half < 2; half++) {
                int r = mrow + mi * 16 + half * 8;
                const float* xr = x + (size_t)r * HD + h0 + cloc;
                #pragma unroll
                for (int nj = 0; nj < 4; nj++) {
                    float2 xv = *reinterpret_cast<const float2*>(xr + nj * 8);
                    cs[nj*2+0] += acc[mi][nj][half*2+0] * xv.x;
                    cs[nj*2+1] += acc[mi][nj][half*2+1] * xv.y;
                }
            }
        #pragma unroll
        for (int nj = 0; nj < 4; nj++) {
            atomicAdd(&suc[cloc + nj * 8],     cs[nj*2+0]);
            atomicAdd(&suc[cloc + nj * 8 + 1], cs[nj*2+1]);
        }
        __syncthreads();
        if (tid < 128)
            atomicAdd(&g_uC[(m0 >> 11) * HD + h0 + tid], suc[tid]);
    } else {                                    // residual -> bf16
        const int cb = n0 - 2048;
        #pragma unroll
        for (int mi = 0; mi < 4; mi++)
            #pragma unroll
            for (int nj = 0; nj < 4; nj++) {
                int r = mrow + mi * 16;
                int c = cb + cloc + nj * 8;
                *reinterpret_cast<uint32_t*>(g_resb + (size_t)r * HD + c) =
                    pack_bf2(acc[mi][nj][0], acc[mi][nj][1]);
                *reinterpret_cast<uint32_t*>(g_resb + (size_t)(r + 8) * HD + c) =
                    pack_bf2(acc[mi][nj][2], acc[mi][nj][3]);
            }
    }
}

// ---------------- fused cumsum + combine ----------------
__global__ void __launch_bounds__(1024) final_kernel(const float* __restrict__ Aa,
                                                     const float* __restrict__ Bp,
                                                     const float* __restrict__ Dp,
                                                     float* __restrict__ out) {
    __shared__ float sd[32][33];
    __shared__ float sr[32][33];
    __shared__ float sy[32][33];
    const int tx = threadIdx.x, ty = threadIdx.y;
    const int h0 = blockIdx.x * 32;
    const int b  = blockIdx.y;
    const int w    = ty;
    const int lane = tx;
    const float A1  = Aa[h0 + w];
    const float B1  = Bp[h0 + w];
    const float Dv  = Dp[0];
    const float uCv = g_uC  [b * HD + h0 + w];
    const float Cv  = g_Csum[b * HD + h0 + w];
    const size_t base = (size_t)b * LD * HD;
    float carry = 0.f;

    for (int lt = 0; lt < LD; lt += 32) {
        size_t off = base + (size_t)(lt + ty) * HD + h0 + tx;
        sd[ty][tx] = g_delta[off];
        sr[ty][tx] = __bfloat162float(g_resb[off]);
        __syncthreads();
        float dv = sd[lane][w];
        float v  = dv * B1;
        #pragma unroll
        for (int o = 1; o < 32; o <<= 1) {
            float nb = __shfl_up_sync(0xffffffffu, v, o);
            if (lane >= o) v += nb;
        }
        float dB = carry + v;
        carry += __shfl_sync(0xffffffffu, v, 31);
        float dA = expf(dv * A1) * B1;
        sy[lane][w] = dA * uCv + dB * Cv + sr[lane][w] * Dv;
        __syncthreads();
        out[off] = sy[ty][tx];
    }
}

// ---------------- launch ----------------
extern "C" void kernel_launch(void* const* d_in, const int* in_sizes, int n_in,
                              void* d_out, int out_size) {
    (void)in_sizes; (void)n_in; (void)out_size;
    const float* x  = (const float*)d_in[0];
    const float* Wp = (const float*)d_in[1];
    const float* A  = (const float*)d_in[2];
    const float* Bp = (const float*)d_in[3];
    const float* D  = (const float*)d_in[4];
    const float* Wd = (const float*)d_in[5];
    const float* bd = (const float*)d_in[6];
    float* out = (float*)d_out;

    cudaFuncSetAttribute(gemm_mma, cudaFuncAttributeMaxDynamicSharedMemorySize, GEMM_SMEM);

    zero_kernel<<<16, 256>>>();
    colsum_kernel<<<dim3(HD / 128, BATCH, LD / 128), 128>>>(x);
    csum_kernel<<<512, 256>>>(Wp);
    conv_x_kernel<<<4096, 256>>>(x);
    conv_wp_kernel<<<1024, 256>>>(Wp);
    conv_w1t_kernel<<<dim3(32, 32), dim3(32, 8)>>>(Wp);
    conv_wd_kernel<<<512, 256>>>(Wd);
    gemm_mma<<<dim3(8, 8),  256, GEMM_SMEM>>>(x, bd, 1);   // W_eff = W_delta @ W1
    gemm_mma<<<dim3(24, 64), 256, GEMM_SMEM>>>(x, bd, 0);  // main fused GEMM
    final_kernel<<<dim3(HD / 32, BATCH), dim3(32, 32)>>>(A, Bp, D, out);
}

// round 6
// speedup vs baseline: 3.8794x; 1.0837x over previous
#include <cuda_runtime.h>
#include <cuda_bf16.h>
#include <cstdint>
#include <math.h>

#define HD   1024
#define LD   2048
#define BATCH 4
#define M_TOTAL 8192

// ---------------- scratch (no allocations allowed) ----------------
__device__ __align__(16) __nv_bfloat16 g_xb [(size_t)M_TOTAL * HD];
__device__ __align__(16) __nv_bfloat16 g_Wpb[(size_t)3072 * HD];  // [0,1024)=W_eff, [1024,2048)=W_C, [2048,3072)=W_res
__device__ __align__(16) __nv_bfloat16 g_W1T[(size_t)HD * HD];
__device__ __align__(16) __nv_bfloat16 g_Wdb[(size_t)HD * HD];
__device__ __align__(16) __nv_bfloat16 g_resb [(size_t)M_TOTAL * HD];
__device__ __align__(16) __nv_bfloat16 g_deltab[(size_t)M_TOTAL * HD];
__device__ float g_uC  [BATCH * HD];
__device__ float g_Csum[BATCH * HD];
__device__ float g_s   [BATCH * HD];

// ---------------- helpers ----------------
__device__ __forceinline__ uint32_t smem_u32(const void* p) {
    uint32_t a;
    asm("{ .reg .u64 t; cvta.to.shared.u64 t, %1; cvt.u32.u64 %0, t; }" : "=r"(a) : "l"(p));
    return a;
}
__device__ __forceinline__ void cp16(uint32_t s, const void* g) {
    asm volatile("cp.async.cg.shared.global [%0], [%1], 16;" :: "r"(s), "l"(g));
}
#define CP_COMMIT() asm volatile("cp.async.commit_group;" ::: "memory")
#define CP_WAIT2()  asm volatile("cp.async.wait_group 2;" ::: "memory")
#define CP_WAIT0()  asm volatile("cp.async.wait_group 0;" ::: "memory")

#define LDSM4(r, addr) \
    asm volatile("ldmatrix.sync.aligned.m8n8.x4.shared.b16 {%0,%1,%2,%3}, [%4];" \
        : "=r"((r)[0]), "=r"((r)[1]), "=r"((r)[2]), "=r"((r)[3]) : "r"(addr))

__device__ __forceinline__ void mma16816(float* c, const uint32_t* a, const uint32_t* b) {
    asm volatile(
        "mma.sync.aligned.m16n8k16.row.col.f32.bf16.bf16.f32 "
        "{%0,%1,%2,%3}, {%4,%5,%6,%7}, {%8,%9}, {%0,%1,%2,%3};"
        : "+f"(c[0]), "+f"(c[1]), "+f"(c[2]), "+f"(c[3])
        : "r"(a[0]), "r"(a[1]), "r"(a[2]), "r"(a[3]), "r"(b[0]), "r"(b[1]));
}
__device__ __forceinline__ uint32_t pack_bf2(float a, float b) {
    __nv_bfloat162 h = __floats2bfloat162_rn(a, b);
    return *reinterpret_cast<uint32_t*>(&h);
}

// ---------------- small kernels ----------------
__global__ void __launch_bounds__(256) zero_kernel() {
    int i = blockIdx.x * 256 + threadIdx.x;
    if (i < BATCH * HD) { g_uC[i] = 0.f; g_s[i] = 0.f; }
}

// fp32 column sums of x (exact path feeding Csum)
__global__ void __launch_bounds__(128) colsum_kernel(const float* __restrict__ x) {
    int h  = blockIdx.x * 128 + threadIdx.x;
    int b  = blockIdx.y;
    int l0 = blockIdx.z * 128;
    const float* p = x + ((size_t)b * LD + l0) * HD + h;
    float s = 0.f;
    #pragma unroll 8
    for (int l = 0; l < 128; l++) s += p[(size_t)l * HD];
    atomicAdd(&g_s[b * HD + h], s);
}

// exact fp32 Csum[b,h] = <W_proj[2048+h,:], g_s[b,:]> (error-critical)
__global__ void __launch_bounds__(256) csum_kernel(const float* __restrict__ Wp) {
    int gw   = blockIdx.x * 8 + (threadIdx.x >> 5);
    int lane = threadIdx.x & 31;
    int b = gw >> 10;
    int h = gw & (HD - 1);
    const float* w = Wp + (size_t)(2 * HD + h) * HD;
    const float* s = g_s + b * HD;
    float acc = 0.f;
    for (int k = lane; k < HD; k += 32) acc += w[k] * s[k];
    #pragma unroll
    for (int off = 16; off; off >>= 1) acc += __shfl_down_sync(0xffffffffu, acc, off);
    if (lane == 0) g_Csum[gw] = acc;
}

// ---------------- fp32 -> bf16 conversions ----------------
__global__ void __launch_bounds__(256) conv_x_kernel(const float* __restrict__ in) {
    size_t i = ((size_t)blockIdx.x * 256 + threadIdx.x) * 8;
    float4 a = *reinterpret_cast<const float4*>(in + i);
    float4 b = *reinterpret_cast<const float4*>(in + i + 4);
    uint4 o;
    o.x = pack_bf2(a.x, a.y); o.y = pack_bf2(a.z, a.w);
    o.z = pack_bf2(b.x, b.y); o.w = pack_bf2(b.z, b.w);
    *reinterpret_cast<uint4*>(g_xb + i) = o;
}
// W_proj rows 2048..4095 -> g_Wpb rows [1024,3072)  (W_C then W_res)
__global__ void __launch_bounds__(256) conv_wp_kernel(const float* __restrict__ Wp) {
    int gid  = blockIdx.x * 256 + threadIdx.x;
    int orow = 1024 + (gid >> 7);
    int c    = (gid & 127) * 8;
    const float* in = Wp + (size_t)(orow + 1024) * HD + c;
    float4 a = *reinterpret_cast<const float4*>(in);
    float4 b = *reinterpret_cast<const float4*>(in + 4);
    uint4 o;
    o.x = pack_bf2(a.x, a.y); o.y = pack_bf2(a.z, a.w);
    o.z = pack_bf2(b.x, b.y); o.w = pack_bf2(b.z, b.w);
    *reinterpret_cast<uint4*>(g_Wpb + (size_t)orow * HD + c) = o;
}
// W1 = W_proj rows [0,1024): transpose-convert -> g_W1T[n][j] = bf16(W1[j][n])
__global__ void __launch_bounds__(256) conv_w1t_kernel(const float* __restrict__ Wp) {
    __shared__ float tile[32][33];
    const int tx = threadIdx.x, ty = threadIdx.y;       // 32 x 8
    const int bx = blockIdx.x * 32, by = blockIdx.y * 32;
    #pragma unroll
    for (int p = 0; p < 4; p++)
        tile[ty + p * 8][tx] = Wp[(size_t)(by + ty + p * 8) * HD + bx + tx];
    __syncthreads();
    #pragma unroll
    for (int p = 0; p < 4; p++) {
        int r = ty + p * 8;
        g_W1T[(size_t)(bx + r) * HD + by + tx] = __float2bfloat16(tile[tx][r]);
    }
}
__global__ void __launch_bounds__(256) conv_wd_kernel(const float* __restrict__ Wd) {
    size_t i = ((size_t)blockIdx.x * 256 + threadIdx.x) * 8;
    float4 a = *reinterpret_cast<const float4*>(Wd + i);
    float4 b = *reinterpret_cast<const float4*>(Wd + i + 4);
    uint4 o;
    o.x = pack_bf2(a.x, a.y); o.y = pack_bf2(a.z, a.w);
    o.z = pack_bf2(b.x, b.y); o.w = pack_bf2(b.z, b.w);
    *reinterpret_cast<uint4*>(g_Wdb + i) = o;
}

// ---------------- bf16 mma.sync GEMM, 4-stage cp.async pipeline ----------------
// Block 128x128, K-chunk 32 (2 k16 steps), 8 warps (2x4), warp tile 64x32.
// mode 0: main GEMM  A=g_xb, B=g_Wpb; n0<1024: delta=softplus(.+bd) -> bf16
//                    n0 in [1024,2048): Cs -> fused uC; n0>=2048: residual -> bf16
// mode 1: W_eff GEMM A=g_Wdb, B=g_W1T; store bf16 -> g_Wpb rows [0,1024)
constexpr int STAGE_BYTES = 16384;
constexpr int GEMM_SMEM   = 1024 + 4 * STAGE_BYTES;

__global__ void __launch_bounds__(256, 2)
gemm_mma(const float* __restrict__ bd, int mode) {
    extern __shared__ char smem[];
    float* suc = reinterpret_cast<float*>(smem);
    const uint32_t sdata = smem_u32(smem) + 1024;

    const int tid  = threadIdx.x;
    const int lane = tid & 31;
    const int warp = tid >> 5;
    const int wm   = warp >> 2;
    const int wn   = warp & 3;
    const int m0   = blockIdx.y * 128;
    const int n0   = blockIdx.x * 128;

    const __nv_bfloat16* Ab = mode ? g_Wdb : g_xb;
    const __nv_bfloat16* Bb = mode ? g_W1T : g_Wpb;

    if (tid < 128) suc[tid] = 0.f;

    uint32_t offA[2][4];
    #pragma unroll
    for (int ks = 0; ks < 2; ks++)
        #pragma unroll
        for (int mi = 0; mi < 4; mi++) {
            int row = wm * 64 + mi * 16 + (lane & 15);
            int c16 = ks * 2 + (lane >> 4);
            offA[ks][mi] = row * 64 + ((c16 ^ ((row >> 1) & 3)) << 4);
        }
    uint32_t offB[2][2];
    #pragma unroll
    for (int ks = 0; ks < 2; ks++)
        #pragma unroll
        for (int np = 0; np < 2; np++) {
            int row = wn * 32 + np * 16 + (lane & 7) + ((lane & 16) >> 1);
            int c16 = ks * 2 + ((lane >> 3) & 1);
            offB[ks][np] = row * 64 + ((c16 ^ ((row >> 1) & 3)) << 4);
        }

    float acc[4][4][4];
    #pragma unroll
    for (int i = 0; i < 4; i++)
        #pragma unroll
        for (int j = 0; j < 4; j++)
            #pragma unroll
            for (int e = 0; e < 4; e++) acc[i][j][e] = 0.f;

    auto load_chunk = [&](int c) {
        const uint32_t sA = sdata + (c & 3) * STAGE_BYTES;
        const uint32_t sB = sA + 8192;
        const __nv_bfloat16* gA = Ab + (size_t)m0 * HD + c * 32;
        const __nv_bfloat16* gB = Bb + (size_t)n0 * HD + c * 32;
        #pragma unroll
        for (int it = 0; it < 2; it++) {
            int seg = tid + it * 256;
            int row = seg >> 2;
            int c16 = seg & 3;
            uint32_t off = row * 64 + ((c16 ^ ((row >> 1) & 3)) << 4);
            cp16(sA + off, gA + (size_t)row * HD + c16 * 8);
            cp16(sB + off, gB + (size_t)row * HD + c16 * 8);
        }
        CP_COMMIT();
    };

    load_chunk(0); load_chunk(1); load_chunk(2);

    #pragma unroll 1
    for (int k = 0; k < 32; k++) {
        if (k <= 28) { CP_WAIT2(); } else { CP_WAIT0(); }
        __syncthreads();
        if (k <= 28) load_chunk(k + 3);

        const uint32_t sA = sdata + (k & 3) * STAGE_BYTES;
        const uint32_t sB = sA + 8192;
        #pragma unroll
        for (int ks = 0; ks < 2; ks++) {
            uint32_t a[4][4], b[4][2];
            #pragma unroll
            for (int mi = 0; mi < 4; mi++) LDSM4(a[mi], sA + offA[ks][mi]);
            #pragma unroll
            for (int np = 0; np < 2; np++) {
                uint32_t r[4];
                LDSM4(r, sB + offB[ks][np]);
                b[np*2+0][0] = r[0]; b[np*2+0][1] = r[1];
                b[np*2+1][0] = r[2]; b[np*2+1][1] = r[3];
            }
            #pragma unroll
            for (int mi = 0; mi < 4; mi++)
                #pragma unroll
                for (int nj = 0; nj < 4; nj++)
                    mma16816(acc[mi][nj], a[mi], b[nj]);
        }
    }

    // -------- epilogue (register-direct) --------
    const int mrow = m0 + wm * 64 + (lane >> 2);
    const int cloc = wn * 32 + (lane & 3) * 2;

    if (mode == 1) {                            // W_eff -> bf16 g_Wpb[0,1024)
        #pragma unroll
        for (int mi = 0; mi < 4; mi++)
            #pragma unroll
            for (int nj = 0; nj < 4; nj++) {
                int r = mrow + mi * 16;
                int c = n0 + cloc + nj * 8;
                *reinterpret_cast<uint32_t*>(g_Wpb + (size_t)r * HD + c) =
                    pack_bf2(acc[mi][nj][0], acc[mi][nj][1]);
                *reinterpret_cast<uint32_t*>(g_Wpb + (size_t)(r + 8) * HD + c) =
                    pack_bf2(acc[mi][nj][2], acc[mi][nj][3]);
            }
    } else if (n0 < 1024) {                     // delta = softplus(. + bd) -> bf16
        #pragma unroll
        for (int mi = 0; mi < 4; mi++)
            #pragma unroll
            for (int nj = 0; nj < 4; nj++) {
                int r = mrow + mi * 16;
                int c = n0 + cloc + nj * 8;
                float b0 = bd[c], b1 = bd[c + 1];
                float v0 = acc[mi][nj][0] + b0;
                float v1 = acc[mi][nj][1] + b1;
                float v2 = acc[mi][nj][2] + b0;
                float v3 = acc[mi][nj][3] + b1;
                v0 = (v0 > 20.f) ? v0 : log1pf(expf(v0));
                v1 = (v1 > 20.f) ? v1 : log1pf(expf(v1));
                v2 = (v2 > 20.f) ? v2 : log1pf(expf(v2));
                v3 = (v3 > 20.f) ? v3 : log1pf(expf(v3));
                *reinterpret_cast<uint32_t*>(g_deltab + (size_t)r * HD + c) = pack_bf2(v0, v1);
                *reinterpret_cast<uint32_t*>(g_deltab + (size_t)(r + 8) * HD + c) = pack_bf2(v2, v3);
            }
    } else if (n0 < 2048) {                     // Cs: fused uC reduction (bf16 x)
        const int h0 = n0 - 1024;
        float cs[8];
        #pragma unroll
        for (int e = 0; e < 8; e++) cs[e] = 0.f;
        #pragma unroll
        for (int mi = 0; mi < 4; mi++)
            #pragma unroll
            for (int half = 0; half < 2; half++) {
                int r = mrow + mi * 16 + half * 8;
                const __nv_bfloat16* xr = g_xb + (size_t)r * HD + h0 + cloc;
                #pragma unroll
                for (int nj = 0; nj < 4; nj++) {
                    __nv_bfloat162 xv =
                        *reinterpret_cast<const __nv_bfloat162*>(xr + nj * 8);
                    cs[nj*2+0] += acc[mi][nj][half*2+0] * __bfloat162float(xv.x);
                    cs[nj*2+1] += acc[mi][nj][half*2+1] * __bfloat162float(xv.y);
                }
            }
        #pragma unroll
        for (int nj = 0; nj < 4; nj++) {
            atomicAdd(&suc[cloc + nj * 8],     cs[nj*2+0]);
            atomicAdd(&suc[cloc + nj * 8 + 1], cs[nj*2+1]);
        }
        __syncthreads();
        if (tid < 128)
            atomicAdd(&g_uC[(m0 >> 11) * HD + h0 + tid], suc[tid]);
    } else {                                    // residual -> bf16
        const int cb = n0 - 2048;
        #pragma unroll
        for (int mi = 0; mi < 4; mi++)
            #pragma unroll
            for (int nj = 0; nj < 4; nj++) {
                int r = mrow + mi * 16;
                int c = cb + cloc + nj * 8;
                *reinterpret_cast<uint32_t*>(g_resb + (size_t)r * HD + c) =
                    pack_bf2(acc[mi][nj][0], acc[mi][nj][1]);
                *reinterpret_cast<uint32_t*>(g_resb + (size_t)(r + 8) * HD + c) =
                    pack_bf2(acc[mi][nj][2], acc[mi][nj][3]);
            }
    }
}

// ---------------- fused cumsum + combine ----------------
__global__ void __launch_bounds__(1024) final_kernel(const float* __restrict__ Aa,
                                                     const float* __restrict__ Bp,
                                                     const float* __restrict__ Dp,
                                                     float* __restrict__ out) {
    __shared__ float sd[32][33];
    __shared__ float sr[32][33];
    __shared__ float sy[32][33];
    const int tx = threadIdx.x, ty = threadIdx.y;
    const int h0 = blockIdx.x * 32;
    const int b  = blockIdx.y;
    const int w    = ty;
    const int lane = tx;
    const float A1  = Aa[h0 + w];
    const float B1  = Bp[h0 + w];
    const float Dv  = Dp[0];
    const float uCv = g_uC  [b * HD + h0 + w];
    const float Cv  = g_Csum[b * HD + h0 + w];
    const size_t base = (size_t)b * LD * HD;
    float carry = 0.f;

    for (int lt = 0; lt < LD; lt += 32) {
        size_t off = base + (size_t)(lt + ty) * HD + h0 + tx;
        sd[ty][tx] = __bfloat162float(g_deltab[off]);
        sr[ty][tx] = __bfloat162float(g_resb[off]);
        __syncthreads();
        float dv = sd[lane][w];
        float v  = dv * B1;
        #pragma unroll
        for (int o = 1; o < 32; o <<= 1) {
            float nb = __shfl_up_sync(0xffffffffu, v, o);
            if (lane >= o) v += nb;
        }
        float dB = carry + v;
        carry += __shfl_sync(0xffffffffu, v, 31);
        float dA = expf(dv * A1) * B1;
        sy[lane][w] = dA * uCv + dB * Cv + sr[lane][w] * Dv;
        __syncthreads();
        out[off] = sy[ty][tx];
    }
}

// ---------------- launch ----------------
extern "C" void kernel_launch(void* const* d_in, const int* in_sizes, int n_in,
                              void* d_out, int out_size) {
    (void)in_sizes; (void)n_in; (void)out_size;
    const float* x  = (const float*)d_in[0];
    const float* Wp = (const float*)d_in[1];
    const float* A  = (const float*)d_in[2];
    const float* Bp = (const float*)d_in[3];
    const float* D  = (const float*)d_in[4];
    const float* Wd = (const float*)d_in[5];
    const float* bd = (const float*)d_in[6];
    float* out = (float*)d_out;

    cudaFuncSetAttribute(gemm_mma, cudaFuncAttributeMaxDynamicSharedMemorySize, GEMM_SMEM);

    zero_kernel<<<16, 256>>>();
    colsum_kernel<<<dim3(HD / 128, BATCH, LD / 128), 128>>>(x);
    csum_kernel<<<512, 256>>>(Wp);
    conv_x_kernel<<<4096, 256>>>(x);
    conv_wp_kernel<<<1024, 256>>>(Wp);
    conv_w1t_kernel<<<dim3(32, 32), dim3(32, 8)>>>(Wp);
    conv_wd_kernel<<<512, 256>>>(Wd);
    gemm_mma<<<dim3(8, 8),  256, GEMM_SMEM>>>(bd, 1);   // W_eff = W_delta @ W1
    gemm_mma<<<dim3(24, 64), 256, GEMM_SMEM>>>(bd, 0);  // main fused GEMM
    final_kernel<<<dim3(HD / 32, BATCH), dim3(32, 32)>>>(A, Bp, D, out);
}

// round 7
// speedup vs baseline: 4.1091x; 1.0592x over previous
#include <cuda_runtime.h>
#include <cuda_bf16.h>
#include <cstdint>
#include <math.h>

#define HD   1024
#define LD   2048
#define BATCH 4
#define M_TOTAL 8192

// ---------------- scratch (no allocations allowed) ----------------
__device__ __align__(16) __nv_bfloat16 g_xb [(size_t)M_TOTAL * HD];
__device__ __align__(16) __nv_bfloat16 g_Wpb[(size_t)3072 * HD];  // [0,1024)=W_eff, [1024,2048)=W_C, [2048,3072)=W_res
__device__ __align__(16) __nv_bfloat16 g_W1T[(size_t)HD * HD];
__device__ __align__(16) __nv_bfloat16 g_Wdb[(size_t)HD * HD];
__device__ __align__(16) __nv_bfloat16 g_resb [(size_t)M_TOTAL * HD];
__device__ __align__(16) __nv_bfloat16 g_deltab[(size_t)M_TOTAL * HD];
__device__ float g_uC  [BATCH * HD];
__device__ float g_Csum[BATCH * HD];
__device__ float g_s   [BATCH * HD];

// ---------------- helpers ----------------
__device__ __forceinline__ uint32_t smem_u32(const void* p) {
    uint32_t a;
    asm("{ .reg .u64 t; cvta.to.shared.u64 t, %1; cvt.u32.u64 %0, t; }" : "=r"(a) : "l"(p));
    return a;
}
__device__ __forceinline__ void cp16(uint32_t s, const void* g) {
    asm volatile("cp.async.cg.shared.global [%0], [%1], 16;" :: "r"(s), "l"(g));
}
#define CP_COMMIT() asm volatile("cp.async.commit_group;" ::: "memory")
#define CP_WAIT1()  asm volatile("cp.async.wait_group 1;" ::: "memory")
#define CP_WAIT0()  asm volatile("cp.async.wait_group 0;" ::: "memory")

#define LDSM4(r, addr) \
    asm volatile("ldmatrix.sync.aligned.m8n8.x4.shared.b16 {%0,%1,%2,%3}, [%4];" \
        : "=r"((r)[0]), "=r"((r)[1]), "=r"((r)[2]), "=r"((r)[3]) : "r"(addr))

__device__ __forceinline__ void mma16816(float* c, const uint32_t* a, const uint32_t* b) {
    asm volatile(
        "mma.sync.aligned.m16n8k16.row.col.f32.bf16.bf16.f32 "
        "{%0,%1,%2,%3}, {%4,%5,%6,%7}, {%8,%9}, {%0,%1,%2,%3};"
        : "+f"(c[0]), "+f"(c[1]), "+f"(c[2]), "+f"(c[3])
        : "r"(a[0]), "r"(a[1]), "r"(a[2]), "r"(a[3]), "r"(b[0]), "r"(b[1]));
}
__device__ __forceinline__ uint32_t pack_bf2(float a, float b) {
    __nv_bfloat162 h = __floats2bfloat162_rn(a, b);
    return *reinterpret_cast<uint32_t*>(&h);
}

// ---------------- small kernels ----------------
__global__ void __launch_bounds__(256) zero_kernel() {
    int i = blockIdx.x * 256 + threadIdx.x;
    if (i < BATCH * HD) { g_uC[i] = 0.f; g_s[i] = 0.f; }
}

// Fused: x -> bf16 conversion + fp32 column sums (x read exactly once)
// grid (HD/512, BATCH, LD/64), block 256; thread handles 2 h-columns, 64 l's.
__global__ void __launch_bounds__(256) convx_colsum_kernel(const float* __restrict__ x) {
    const int h  = (blockIdx.x * 256 + threadIdx.x) * 2;
    const int b  = blockIdx.y;
    const int l0 = blockIdx.z * 64;
    const float* p = x + ((size_t)b * LD + l0) * HD + h;
    __nv_bfloat16* q = g_xb + ((size_t)b * LD + l0) * HD + h;
    float s0 = 0.f, s1 = 0.f;
    #pragma unroll 8
    for (int l = 0; l < 64; l++) {
        float2 v = *reinterpret_cast<const float2*>(p + (size_t)l * HD);
        s0 += v.x; s1 += v.y;
        *reinterpret_cast<uint32_t*>(q + (size_t)l * HD) = pack_bf2(v.x, v.y);
    }
    atomicAdd(&g_s[b * HD + h],     s0);
    atomicAdd(&g_s[b * HD + h + 1], s1);
}

// exact fp32 Csum[b,h] = <W_proj[2048+h,:], g_s[b,:]> (error-critical)
__global__ void __launch_bounds__(256) csum_kernel(const float* __restrict__ Wp) {
    int gw   = blockIdx.x * 8 + (threadIdx.x >> 5);
    int lane = threadIdx.x & 31;
    int b = gw >> 10;
    int h = gw & (HD - 1);
    const float* w = Wp + (size_t)(2 * HD + h) * HD;
    const float* s = g_s + b * HD;
    float acc = 0.f;
    for (int k = lane; k < HD; k += 32) acc += w[k] * s[k];
    #pragma unroll
    for (int off = 16; off; off >>= 1) acc += __shfl_down_sync(0xffffffffu, acc, off);
    if (lane == 0) g_Csum[gw] = acc;
}

// Merged weight conversion: rows [0,2048) -> g_Wpb[1024..3072) from W_proj[2048..4096),
// rows [2048,3072) -> g_Wdb from W_delta.
__global__ void __launch_bounds__(256) conv_w_kernel(const float* __restrict__ Wp,
                                                     const float* __restrict__ Wd) {
    int gid = blockIdx.x * 256 + threadIdx.x;       // 3072*128 threads
    int row = gid >> 7;
    int c   = (gid & 127) * 8;
    const float* in;
    __nv_bfloat16* outp;
    if (row < 2048) {
        in   = Wp + (size_t)(row + 2048) * HD + c;
        outp = g_Wpb + (size_t)(row + 1024) * HD + c;
    } else {
        in   = Wd + (size_t)(row - 2048) * HD + c;
        outp = g_Wdb + (size_t)(row - 2048) * HD + c;
    }
    float4 a = *reinterpret_cast<const float4*>(in);
    float4 b = *reinterpret_cast<const float4*>(in + 4);
    uint4 o;
    o.x = pack_bf2(a.x, a.y); o.y = pack_bf2(a.z, a.w);
    o.z = pack_bf2(b.x, b.y); o.w = pack_bf2(b.z, b.w);
    *reinterpret_cast<uint4*>(outp) = o;
}

// W1 = W_proj rows [0,1024): transpose-convert -> g_W1T[n][j] = bf16(W1[j][n])
__global__ void __launch_bounds__(256) conv_w1t_kernel(const float* __restrict__ Wp) {
    __shared__ float tile[32][33];
    const int tx = threadIdx.x, ty = threadIdx.y;       // 32 x 8
    const int bx = blockIdx.x * 32, by = blockIdx.y * 32;
    #pragma unroll
    for (int p = 0; p < 4; p++)
        tile[ty + p * 8][tx] = Wp[(size_t)(by + ty + p * 8) * HD + bx + tx];
    __syncthreads();
    #pragma unroll
    for (int p = 0; p < 4; p++) {
        int r = ty + p * 8;
        g_W1T[(size_t)(bx + r) * HD + by + tx] = __float2bfloat16(tile[tx][r]);
    }
}

// ---------------- bf16 mma.sync GEMM, K-chunk 64, 3-stage cp.async pipeline ----------------
// Block 128x128, K-chunk 64 (4 k16 steps), 8 warps (2x4), warp tile 64x32.
// Stage: A 128x64 bf16 (16KB, XOR-8 swizzled 128B rows) + B same. 3 stages = 96KB.
// mode 0: main GEMM  A=g_xb, B=g_Wpb; n0<1024: delta=softplus(.+bd) -> bf16
//                    n0 in [1024,2048): Cs -> fused uC; n0>=2048: residual -> bf16
// mode 1: W_eff GEMM A=g_Wdb, B=g_W1T; store bf16 -> g_Wpb rows [0,1024)
constexpr int STAGE_BYTES = 32768;
constexpr int GEMM_SMEM   = 1024 + 3 * STAGE_BYTES;

__global__ void __launch_bounds__(256, 2)
gemm_mma(const float* __restrict__ bd, int mode) {
    extern __shared__ char smem[];
    float* suc = reinterpret_cast<float*>(smem);
    const uint32_t sdata = smem_u32(smem) + 1024;

    const int tid  = threadIdx.x;
    const int lane = tid & 31;
    const int warp = tid >> 5;
    const int wm   = warp >> 2;
    const int wn   = warp & 3;
    const int m0   = blockIdx.y * 128;
    const int n0   = blockIdx.x * 128;

    const __nv_bfloat16* Ab = mode ? g_Wdb : g_xb;
    const __nv_bfloat16* Bb = mode ? g_W1T : g_Wpb;

    if (tid < 128) suc[tid] = 0.f;

    // ldmatrix row bases (row*128) and swizzle key x7 = row & 7 (mi/np invariant)
    const uint32_t x7  = lane & 7;
    const uint32_t hiA = lane >> 4;          // 0/1
    const uint32_t hiB = (lane >> 3) & 1;    // 0/1
    uint32_t rA[4], rB[2];
    #pragma unroll
    for (int mi = 0; mi < 4; mi++)
        rA[mi] = (uint32_t)(wm * 64 + mi * 16 + (lane & 15)) * 128;
    #pragma unroll
    for (int np = 0; np < 2; np++)
        rB[np] = (uint32_t)(wn * 32 + np * 16 + (lane & 7) + ((lane & 16) >> 1)) * 128;

    float acc[4][4][4];
    #pragma unroll
    for (int i = 0; i < 4; i++)
        #pragma unroll
        for (int j = 0; j < 4; j++)
            #pragma unroll
            for (int e = 0; e < 4; e++) acc[i][j][e] = 0.f;

    auto load_chunk = [&](int c) {
        const uint32_t sA = sdata + (c % 3) * STAGE_BYTES;
        const uint32_t sB = sA + 16384;
        const __nv_bfloat16* gA = Ab + (size_t)m0 * HD + c * 64;
        const __nv_bfloat16* gB = Bb + (size_t)n0 * HD + c * 64;
        #pragma unroll
        for (int it = 0; it < 4; it++) {
            int seg = tid + it * 256;            // 1024 segs: 128 rows x 8 c16
            int row = seg >> 3;
            int c16 = seg & 7;
            uint32_t off = row * 128 + ((c16 ^ (row & 7)) << 4);
            cp16(sA + off, gA + (size_t)row * HD + c16 * 8);
        }
        #pragma unroll
        for (int it = 0; it < 4; it++) {
            int seg = tid + it * 256;
            int row = seg >> 3;
            int c16 = seg & 7;
            uint32_t off = row * 128 + ((c16 ^ (row & 7)) << 4);
            cp16(sB + off, gB + (size_t)row * HD + c16 * 8);
        }
        CP_COMMIT();
    };

    load_chunk(0); load_chunk(1);

    #pragma unroll 1
    for (int k = 0; k < 16; k++) {
        if (k < 14) { CP_WAIT1(); } else { CP_WAIT0(); }
        __syncthreads();
        if (k + 2 < 16) load_chunk(k + 2);

        const uint32_t sA = sdata + (k % 3) * STAGE_BYTES;
        const uint32_t sB = sA + 16384;
        #pragma unroll
        for (int ks = 0; ks < 4; ks++) {
            uint32_t a[4][4], b[4][2];
            const uint32_t cA = (((ks * 2 + hiA) ^ x7) << 4);
            const uint32_t cB = (((ks * 2 + hiB) ^ x7) << 4);
            #pragma unroll
            for (int mi = 0; mi < 4; mi++) LDSM4(a[mi], sA + rA[mi] + cA);
            #pragma unroll
            for (int np = 0; np < 2; np++) {
                uint32_t r[4];
                LDSM4(r, sB + rB[np] + cB);
                b[np*2+0][0] = r[0]; b[np*2+0][1] = r[1];
                b[np*2+1][0] = r[2]; b[np*2+1][1] = r[3];
            }
            #pragma unroll
            for (int mi = 0; mi < 4; mi++)
                #pragma unroll
                for (int nj = 0; nj < 4; nj++)
                    mma16816(acc[mi][nj], a[mi], b[nj]);
        }
    }

    // -------- epilogue (register-direct) --------
    const int mrow = m0 + wm * 64 + (lane >> 2);
    const int cloc = wn * 32 + (lane & 3) * 2;

    if (mode == 1) {                            // W_eff -> bf16 g_Wpb[0,1024)
        #pragma unroll
        for (int mi = 0; mi < 4; mi++)
            #pragma unroll
            for (int nj = 0; nj < 4; nj++) {
                int r = mrow + mi * 16;
                int c = n0 + cloc + nj * 8;
                *reinterpret_cast<uint32_t*>(g_Wpb + (size_t)r * HD + c) =
                    pack_bf2(acc[mi][nj][0], acc[mi][nj][1]);
                *reinterpret_cast<uint32_t*>(g_Wpb + (size_t)(r + 8) * HD + c) =
                    pack_bf2(acc[mi][nj][2], acc[mi][nj][3]);
            }
    } else if (n0 < 1024) {                     // delta = softplus(. + bd) -> bf16
        #pragma unroll
        for (int mi = 0; mi < 4; mi++)
            #pragma unroll
            for (int nj = 0; nj < 4; nj++) {
                int r = mrow + mi * 16;
                int c = n0 + cloc + nj * 8;
                float b0 = bd[c], b1 = bd[c + 1];
                float v0 = acc[mi][nj][0] + b0;
                float v1 = acc[mi][nj][1] + b1;
                float v2 = acc[mi][nj][2] + b0;
                float v3 = acc[mi][nj][3] + b1;
                v0 = (v0 > 20.f) ? v0 : log1pf(expf(v0));
                v1 = (v1 > 20.f) ? v1 : log1pf(expf(v1));
                v2 = (v2 > 20.f) ? v2 : log1pf(expf(v2));
                v3 = (v3 > 20.f) ? v3 : log1pf(expf(v3));
                *reinterpret_cast<uint32_t*>(g_deltab + (size_t)r * HD + c) = pack_bf2(v0, v1);
                *reinterpret_cast<uint32_t*>(g_deltab + (size_t)(r + 8) * HD + c) = pack_bf2(v2, v3);
            }
    } else if (n0 < 2048) {                     // Cs: fused uC reduction (bf16 x)
        const int h0 = n0 - 1024;
        float cs[8];
        #pragma unroll
        for (int e = 0; e < 8; e++) cs[e] = 0.f;
        #pragma unroll
        for (int mi = 0; mi < 4; mi++)
            #pragma unroll
            for (int half = 0; half < 2; half++) {
                int r = mrow + mi * 16 + half * 8;
                const __nv_bfloat16* xr = g_xb + (size_t)r * HD + h0 + cloc;
                #pragma unroll
                for (int nj = 0; nj < 4; nj++) {
                    __nv_bfloat162 xv =
                        *reinterpret_cast<const __nv_bfloat162*>(xr + nj * 8);
                    cs[nj*2+0] += acc[mi][nj][half*2+0] * __bfloat162float(xv.x);
                    cs[nj*2+1] += acc[mi][nj][half*2+1] * __bfloat162float(xv.y);
                }
            }
        #pragma unroll
        for (int nj = 0; nj < 4; nj++) {
            atomicAdd(&suc[cloc + nj * 8],     cs[nj*2+0]);
            atomicAdd(&suc[cloc + nj * 8 + 1], cs[nj*2+1]);
        }
        __syncthreads();
        if (tid < 128)
            atomicAdd(&g_uC[(m0 >> 11) * HD + h0 + tid], suc[tid]);
    } else {                                    // residual -> bf16
        const int cb = n0 - 2048;
        #pragma unroll
        for (int mi = 0; mi < 4; mi++)
            #pragma unroll
            for (int nj = 0; nj < 4; nj++) {
                int r = mrow + mi * 16;
                int c = cb + cloc + nj * 8;
                *reinterpret_cast<uint32_t*>(g_resb + (size_t)r * HD + c) =
                    pack_bf2(acc[mi][nj][0], acc[mi][nj][1]);
                *reinterpret_cast<uint32_t*>(g_resb + (size_t)(r + 8) * HD + c) =
                    pack_bf2(acc[mi][nj][2], acc[mi][nj][3]);
            }
    }
}

// ---------------- fused cumsum + combine ----------------
__global__ void __launch_bounds__(1024) final_kernel(const float* __restrict__ Aa,
                                                     const float* __restrict__ Bp,
                                                     const float* __restrict__ Dp,
                                                     float* __restrict__ out) {
    __shared__ float sd[32][33];
    __shared__ float sr[32][33];
    __shared__ float sy[32][33];
    const int tx = threadIdx.x, ty = threadIdx.y;
    const int h0 = blockIdx.x * 32;
    const int b  = blockIdx.y;
    const int w    = ty;
    const int lane = tx;
    const float A1  = Aa[h0 + w];
    const float B1  = Bp[h0 + w];
    const float Dv  = Dp[0];
    const float uCv = g_uC  [b * HD + h0 + w];
    const float Cv  = g_Csum[b * HD + h0 + w];
    const size_t base = (size_t)b * LD * HD;
    float carry = 0.f;

    for (int lt = 0; lt < LD; lt += 32) {
        size_t off = base + (size_t)(lt + ty) * HD + h0 + tx;
        sd[ty][tx] = __bfloat162float(g_deltab[off]);
        sr[ty][tx] = __bfloat162float(g_resb[off]);
        __syncthreads();
        float dv = sd[lane][w];
        float v  = dv * B1;
        #pragma unroll
        for (int o = 1; o < 32; o <<= 1) {
            float nb = __shfl_up_sync(0xffffffffu, v, o);
            if (lane >= o) v += nb;
        }
        float dB = carry + v;
        carry += __shfl_sync(0xffffffffu, v, 31);
        float dA = expf(dv * A1) * B1;
        sy[lane][w] = dA * uCv + dB * Cv + sr[lane][w] * Dv;
        __syncthreads();
        out[off] = sy[ty][tx];
    }
}

// ---------------- launch ----------------
extern "C" void kernel_launch(void* const* d_in, const int* in_sizes, int n_in,
                              void* d_out, int out_size) {
    (void)in_sizes; (void)n_in; (void)out_size;
    const float* x  = (const float*)d_in[0];
    const float* Wp = (const float*)d_in[1];
    const float* A  = (const float*)d_in[2];
    const float* Bp = (const float*)d_in[3];
    const float* D  = (const float*)d_in[4];
    const float* Wd = (const float*)d_in[5];
    const float* bd = (const float*)d_in[6];
    float* out = (float*)d_out;

    cudaFuncSetAttribute(gemm_mma, cudaFuncAttributeMaxDynamicSharedMemorySize, GEMM_SMEM);

    zero_kernel<<<16, 256>>>();
    convx_colsum_kernel<<<dim3(HD / 512, BATCH, LD / 64), 256>>>(x);
    csum_kernel<<<512, 256>>>(Wp);
    conv_w_kernel<<<1536, 256>>>(Wp, Wd);
    conv_w1t_kernel<<<dim3(32, 32), dim3(32, 8)>>>(Wp);
    gemm_mma<<<dim3(8, 8),  256, GEMM_SMEM>>>(bd, 1);   // W_eff = W_delta @ W1
    gemm_mma<<<dim3(24, 64), 256, GEMM_SMEM>>>(bd, 0);  // main fused GEMM
    final_kernel<<<dim3(HD / 32, BATCH), dim3(32, 32)>>>(A, Bp, D, out);
}

// round 8
// speedup vs baseline: 4.2699x; 1.0391x over previous
#include <cuda_runtime.h>
#include <cuda_bf16.h>
#include <cstdint>
#include <math.h>

#define HD   1024
#define LD   2048
#define BATCH 4
#define M_TOTAL 8192

// ---------------- scratch (no allocations allowed) ----------------
__device__ __align__(16) __nv_bfloat16 g_xb [(size_t)M_TOTAL * HD];
__device__ __align__(16) __nv_bfloat16 g_xT [(size_t)HD * M_TOTAL];      // x transposed: [h][b*L+l]
__device__ __align__(16) __nv_bfloat16 g_Wpb[(size_t)2048 * HD];         // [0,1024)=W_eff, [1024,2048)=W_res
__device__ __align__(16) __nv_bfloat16 g_W1T[(size_t)HD * HD];
__device__ __align__(16) __nv_bfloat16 g_Wdb[(size_t)HD * HD];
__device__ __align__(16) __nv_bfloat16 g_resb [(size_t)M_TOTAL * HD];
__device__ __align__(16) __nv_bfloat16 g_deltab[(size_t)M_TOTAL * HD];
__device__ __align__(16) float g_G[(size_t)BATCH * HD * HD];             // Gram matrices (symmetric, stored full)
__device__ float g_uC  [BATCH * HD];
__device__ float g_Csum[BATCH * HD];
__device__ float g_s   [BATCH * HD];

// ---------------- helpers ----------------
__device__ __forceinline__ uint32_t smem_u32(const void* p) {
    uint32_t a;
    asm("{ .reg .u64 t; cvta.to.shared.u64 t, %1; cvt.u32.u64 %0, t; }" : "=r"(a) : "l"(p));
    return a;
}
__device__ __forceinline__ void cp16(uint32_t s, const void* g) {
    asm volatile("cp.async.cg.shared.global [%0], [%1], 16;" :: "r"(s), "l"(g));
}
#define CP_COMMIT() asm volatile("cp.async.commit_group;" ::: "memory")
#define CP_WAIT1()  asm volatile("cp.async.wait_group 1;" ::: "memory")
#define CP_WAIT0()  asm volatile("cp.async.wait_group 0;" ::: "memory")

#define LDSM4(r, addr) \
    asm volatile("ldmatrix.sync.aligned.m8n8.x4.shared.b16 {%0,%1,%2,%3}, [%4];" \
        : "=r"((r)[0]), "=r"((r)[1]), "=r"((r)[2]), "=r"((r)[3]) : "r"(addr))

__device__ __forceinline__ void mma16816(float* c, const uint32_t* a, const uint32_t* b) {
    asm volatile(
        "mma.sync.aligned.m16n8k16.row.col.f32.bf16.bf16.f32 "
        "{%0,%1,%2,%3}, {%4,%5,%6,%7}, {%8,%9}, {%0,%1,%2,%3};"
        : "+f"(c[0]), "+f"(c[1]), "+f"(c[2]), "+f"(c[3])
        : "r"(a[0]), "r"(a[1]), "r"(a[2]), "r"(a[3]), "r"(b[0]), "r"(b[1]));
}
__device__ __forceinline__ uint32_t pack_bf2(float a, float b) {
    __nv_bfloat162 h = __floats2bfloat162_rn(a, b);
    return *reinterpret_cast<uint32_t*>(&h);
}

// ---------------- small kernels ----------------
__global__ void __launch_bounds__(256) zero_kernel() {
    int i = blockIdx.x * 256 + threadIdx.x;
    if (i < BATCH * HD) g_s[i] = 0.f;
}

// Fused: x -> bf16 (row-major AND transposed) + fp32 column sums. x read once.
// grid (HD/512, BATCH, LD/64), block 256; thread: 2 h-columns x 64 l's.
__global__ void __launch_bounds__(256) convx_colsum_kernel(const float* __restrict__ x) {
    const int h  = (blockIdx.x * 256 + threadIdx.x) * 2;
    const int b  = blockIdx.y;
    const int l0 = blockIdx.z * 64;
    const float* p = x + ((size_t)b * LD + l0) * HD + h;
    __nv_bfloat16* q  = g_xb + ((size_t)b * LD + l0) * HD + h;
    __nv_bfloat16* t0 = g_xT + (size_t)h * M_TOTAL + b * LD + l0;
    __nv_bfloat16* t1 = t0 + M_TOTAL;
    float s0 = 0.f, s1 = 0.f;
    #pragma unroll
    for (int g = 0; g < 8; g++) {
        uint4 r0, r1;
        uint16_t* a0 = reinterpret_cast<uint16_t*>(&r0);
        uint16_t* a1 = reinterpret_cast<uint16_t*>(&r1);
        #pragma unroll
        for (int i = 0; i < 8; i++) {
            int l = g * 8 + i;
            float2 v = *reinterpret_cast<const float2*>(p + (size_t)l * HD);
            s0 += v.x; s1 += v.y;
            uint32_t pk = pack_bf2(v.x, v.y);
            *reinterpret_cast<uint32_t*>(q + (size_t)l * HD) = pk;
            a0[i] = (uint16_t)(pk & 0xffffu);
            a1[i] = (uint16_t)(pk >> 16);
        }
        *reinterpret_cast<uint4*>(t0 + g * 8) = r0;
        *reinterpret_cast<uint4*>(t1 + g * 8) = r1;
    }
    atomicAdd(&g_s[b * HD + h],     s0);
    atomicAdd(&g_s[b * HD + h + 1], s1);
}

// exact fp32 Csum[b,h] = <W_proj[2048+h,:], g_s[b,:]> (error-critical)
__global__ void __launch_bounds__(256) csum_kernel(const float* __restrict__ Wp) {
    int gw   = blockIdx.x * 8 + (threadIdx.x >> 5);
    int lane = threadIdx.x & 31;
    int b = gw >> 10;
    int h = gw & (HD - 1);
    const float* w = Wp + (size_t)(2 * HD + h) * HD;
    const float* s = g_s + b * HD;
    float acc = 0.f;
    for (int k = lane; k < HD; k += 32) acc += w[k] * s[k];
    #pragma unroll
    for (int off = 16; off; off >>= 1) acc += __shfl_down_sync(0xffffffffu, acc, off);
    if (lane == 0) g_Csum[gw] = acc;
}

// uC[b,h] = <W_C[h,:], G_b[h,:]>  (G symmetric, row-coalesced fp32 dot)
__global__ void __launch_bounds__(256) uc_matvec_kernel(const float* __restrict__ Wp) {
    int gw   = blockIdx.x * 8 + (threadIdx.x >> 5);
    int lane = threadIdx.x & 31;
    int b = gw >> 10;
    int h = gw & (HD - 1);
    const float* w = Wp + (size_t)(2 * HD + h) * HD;
    const float* g = g_G + (size_t)b * HD * HD + (size_t)h * HD;
    float acc = 0.f;
    for (int k = lane; k < HD; k += 32) acc += w[k] * g[k];
    #pragma unroll
    for (int off = 16; off; off >>= 1) acc += __shfl_down_sync(0xffffffffu, acc, off);
    if (lane == 0) g_uC[gw] = acc;
}

// Weight conversion: rows [0,1024): W_res (Wp rows 3072+) -> g_Wpb[1024..2048);
//                    rows [1024,2048): W_delta -> g_Wdb.
__global__ void __launch_bounds__(256) conv_w_kernel(const float* __restrict__ Wp,
                                                     const float* __restrict__ Wd) {
    int gid = blockIdx.x * 256 + threadIdx.x;       // 2048*128 threads
    int row = gid >> 7;
    int c   = (gid & 127) * 8;
    const float* in;
    __nv_bfloat16* outp;
    if (row < 1024) {
        in   = Wp + (size_t)(row + 3072) * HD + c;
        outp = g_Wpb + (size_t)(row + 1024) * HD + c;
    } else {
        in   = Wd + (size_t)(row - 1024) * HD + c;
        outp = g_Wdb + (size_t)(row - 1024) * HD + c;
    }
    float4 a = *reinterpret_cast<const float4*>(in);
    float4 b = *reinterpret_cast<const float4*>(in + 4);
    uint4 o;
    o.x = pack_bf2(a.x, a.y); o.y = pack_bf2(a.z, a.w);
    o.z = pack_bf2(b.x, b.y); o.w = pack_bf2(b.z, b.w);
    *reinterpret_cast<uint4*>(outp) = o;
}

// W1 = W_proj rows [0,1024): transpose-convert -> g_W1T[n][j] = bf16(W1[j][n])
__global__ void __launch_bounds__(256) conv_w1t_kernel(const float* __restrict__ Wp) {
    __shared__ float tile[32][33];
    const int tx = threadIdx.x, ty = threadIdx.y;       // 32 x 8
    const int bx = blockIdx.x * 32, by = blockIdx.y * 32;
    #pragma unroll
    for (int p = 0; p < 4; p++)
        tile[ty + p * 8][tx] = Wp[(size_t)(by + ty + p * 8) * HD + bx + tx];
    __syncthreads();
    #pragma unroll
    for (int p = 0; p < 4; p++) {
        int r = ty + p * 8;
        g_W1T[(size_t)(bx + r) * HD + by + tx] = __float2bfloat16(tile[tx][r]);
    }
}

// ---------------- bf16 mma.sync GEMM core constants ----------------
constexpr int STAGE_BYTES = 32768;
constexpr int GEMM_SMEM   = 1024 + 3 * STAGE_BYTES;

// Main / W_eff GEMM. mode 0: A=g_xb, B=g_Wpb (N=2048): n0<1024 delta; else residual.
//                    mode 1: A=g_Wdb, B=g_W1T -> W_eff into g_Wpb[0,1024).
__global__ void __launch_bounds__(256, 2)
gemm_mma(const float* __restrict__ bd, int mode) {
    extern __shared__ char smem[];
    const uint32_t sdata = smem_u32(smem) + 1024;

    const int tid  = threadIdx.x;
    const int lane = tid & 31;
    const int warp = tid >> 5;
    const int wm   = warp >> 2;
    const int wn   = warp & 3;
    const int m0   = blockIdx.y * 128;
    const int n0   = blockIdx.x * 128;

    const __nv_bfloat16* Ab = mode ? g_Wdb : g_xb;
    const __nv_bfloat16* Bb = mode ? g_W1T : g_Wpb;

    const uint32_t x7  = lane & 7;
    const uint32_t hiA = lane >> 4;
    const uint32_t hiB = (lane >> 3) & 1;
    uint32_t rA[4], rB[2];
    #pragma unroll
    for (int mi = 0; mi < 4; mi++)
        rA[mi] = (uint32_t)(wm * 64 + mi * 16 + (lane & 15)) * 128;
    #pragma unroll
    for (int np = 0; np < 2; np++)
        rB[np] = (uint32_t)(wn * 32 + np * 16 + (lane & 7) + ((lane & 16) >> 1)) * 128;

    float acc[4][4][4];
    #pragma unroll
    for (int i = 0; i < 4; i++)
        #pragma unroll
        for (int j = 0; j < 4; j++)
            #pragma unroll
            for (int e = 0; e < 4; e++) acc[i][j][e] = 0.f;

    auto load_chunk = [&](int c) {
        const uint32_t sA = sdata + (c % 3) * STAGE_BYTES;
        const uint32_t sB = sA + 16384;
        const __nv_bfloat16* gA = Ab + (size_t)m0 * HD + c * 64;
        const __nv_bfloat16* gB = Bb + (size_t)n0 * HD + c * 64;
        #pragma unroll
        for (int it = 0; it < 4; it++) {
            int seg = tid + it * 256;
            int row = seg >> 3;
            int c16 = seg & 7;
            uint32_t off = row * 128 + ((c16 ^ (row & 7)) << 4);
            cp16(sA + off, gA + (size_t)row * HD + c16 * 8);
        }
        #pragma unroll
        for (int it = 0; it < 4; it++) {
            int seg = tid + it * 256;
            int row = seg >> 3;
            int c16 = seg & 7;
            uint32_t off = row * 128 + ((c16 ^ (row & 7)) << 4);
            cp16(sB + off, gB + (size_t)row * HD + c16 * 8);
        }
        CP_COMMIT();
    };

    load_chunk(0); load_chunk(1);

    #pragma unroll 1
    for (int k = 0; k < 16; k++) {
        if (k < 14) { CP_WAIT1(); } else { CP_WAIT0(); }
        __syncthreads();
        if (k + 2 < 16) load_chunk(k + 2);

        const uint32_t sA = sdata + (k % 3) * STAGE_BYTES;
        const uint32_t sB = sA + 16384;
        #pragma unroll
        for (int ks = 0; ks < 4; ks++) {
            uint32_t a[4][4], b[4][2];
            const uint32_t cA = (((ks * 2 + hiA) ^ x7) << 4);
            const uint32_t cB = (((ks * 2 + hiB) ^ x7) << 4);
            #pragma unroll
            for (int mi = 0; mi < 4; mi++) LDSM4(a[mi], sA + rA[mi] + cA);
            #pragma unroll
            for (int np = 0; np < 2; np++) {
                uint32_t r[4];
                LDSM4(r, sB + rB[np] + cB);
                b[np*2+0][0] = r[0]; b[np*2+0][1] = r[1];
                b[np*2+1][0] = r[2]; b[np*2+1][1] = r[3];
            }
            #pragma unroll
            for (int mi = 0; mi < 4; mi++)
                #pragma unroll
                for (int nj = 0; nj < 4; nj++)
                    mma16816(acc[mi][nj], a[mi], b[nj]);
        }
    }

    // -------- epilogue (register-direct) --------
    const int mrow = m0 + wm * 64 + (lane >> 2);
    const int cloc = wn * 32 + (lane & 3) * 2;

    if (mode == 1) {                            // W_eff -> bf16 g_Wpb[0,1024)
        #pragma unroll
        for (int mi = 0; mi < 4; mi++)
            #pragma unroll
            for (int nj = 0; nj < 4; nj++) {
                int r = mrow + mi * 16;
                int c = n0 + cloc + nj * 8;
                *reinterpret_cast<uint32_t*>(g_Wpb + (size_t)r * HD + c) =
                    pack_bf2(acc[mi][nj][0], acc[mi][nj][1]);
                *reinterpret_cast<uint32_t*>(g_Wpb + (size_t)(r + 8) * HD + c) =
                    pack_bf2(acc[mi][nj][2], acc[mi][nj][3]);
            }
    } else if (n0 < 1024) {                     // delta = softplus(. + bd) -> bf16
        #pragma unroll
        for (int mi = 0; mi < 4; mi++)
            #pragma unroll
            for (int nj = 0; nj < 4; nj++) {
                int r = mrow + mi * 16;
                int c = n0 + cloc + nj * 8;
                float b0 = bd[c], b1 = bd[c + 1];
                float v0 = acc[mi][nj][0] + b0;
                float v1 = acc[mi][nj][1] + b1;
                float v2 = acc[mi][nj][2] + b0;
                float v3 = acc[mi][nj][3] + b1;
                v0 = (v0 > 20.f) ? v0 : log1pf(expf(v0));
                v1 = (v1 > 20.f) ? v1 : log1pf(expf(v1));
                v2 = (v2 > 20.f) ? v2 : log1pf(expf(v2));
                v3 = (v3 > 20.f) ? v3 : log1pf(expf(v3));
                *reinterpret_cast<uint32_t*>(g_deltab + (size_t)r * HD + c) = pack_bf2(v0, v1);
                *reinterpret_cast<uint32_t*>(g_deltab + (size_t)(r + 8) * HD + c) = pack_bf2(v2, v3);
            }
    } else {                                    // residual -> bf16
        const int cb = n0 - 1024;
        #pragma unroll
        for (int mi = 0; mi < 4; mi++)
            #pragma unroll
            for (int nj = 0; nj < 4; nj++) {
                int r = mrow + mi * 16;
                int c = cb + cloc + nj * 8;
                *reinterpret_cast<uint32_t*>(g_resb + (size_t)r * HD + c) =
                    pack_bf2(acc[mi][nj][0], acc[mi][nj][1]);
                *reinterpret_cast<uint32_t*>(g_resb + (size_t)(r + 8) * HD + c) =
                    pack_bf2(acc[mi][nj][2], acc[mi][nj][3]);
            }
    }
}

// ---------------- Gram GEMM: G_b = x_b^T x_b (upper-triangle tiles + mirror) ----------------
// A = B = g_xT (row stride M_TOTAL), K = 2048 per batch. grid: 4*36 CTAs.
__global__ void __launch_bounds__(256, 2)
gram_mma() {
    extern __shared__ char smem[];
    const uint32_t sdata = smem_u32(smem) + 1024;

    const int tid  = threadIdx.x;
    const int lane = tid & 31;
    const int warp = tid >> 5;
    const int wm   = warp >> 2;
    const int wn   = warp & 3;

    int idx = blockIdx.x % 36;
    const int b = blockIdx.x / 36;
    int mt = 0;
    while (idx >= 8 - mt) { idx -= 8 - mt; mt++; }
    const int nt = mt + idx;
    const int m0 = mt * 128;
    const int n0 = nt * 128;
    const size_t kbase = (size_t)b * LD;

    const uint32_t x7  = lane & 7;
    const uint32_t hiA = lane >> 4;
    const uint32_t hiB = (lane >> 3) & 1;
    uint32_t rA[4], rB[2];
    #pragma unroll
    for (int mi = 0; mi < 4; mi++)
        rA[mi] = (uint32_t)(wm * 64 + mi * 16 + (lane & 15)) * 128;
    #pragma unroll
    for (int np = 0; np < 2; np++)
        rB[np] = (uint32_t)(wn * 32 + np * 16 + (lane & 7) + ((lane & 16) >> 1)) * 128;

    float acc[4][4][4];
    #pragma unroll
    for (int i = 0; i < 4; i++)
        #pragma unroll
        for (int j = 0; j < 4; j++)
            #pragma unroll
            for (int e = 0; e < 4; e++) acc[i][j][e] = 0.f;

    auto load_chunk = [&](int c) {
        const uint32_t sA = sdata + (c % 3) * STAGE_BYTES;
        const uint32_t sB = sA + 16384;
        const __nv_bfloat16* gA = g_xT + (size_t)m0 * M_TOTAL + kbase + c * 64;
        const __nv_bfloat16* gB = g_xT + (size_t)n0 * M_TOTAL + kbase + c * 64;
        #pragma unroll
        for (int it = 0; it < 4; it++) {
            int seg = tid + it * 256;
            int row = seg >> 3;
            int c16 = seg & 7;
            uint32_t off = row * 128 + ((c16 ^ (row & 7)) << 4);
            cp16(sA + off, gA + (size_t)row * M_TOTAL + c16 * 8);
        }
        #pragma unroll
        for (int it = 0; it < 4; it++) {
            int seg = tid + it * 256;
            int row = seg >> 3;
            int c16 = seg & 7;
            uint32_t off = row * 128 + ((c16 ^ (row & 7)) << 4);
            cp16(sB + off, gB + (size_t)row * M_TOTAL + c16 * 8);
        }
        CP_COMMIT();
    };

    load_chunk(0); load_chunk(1);

    #pragma unroll 1
    for (int k = 0; k < 32; k++) {
        if (k < 30) { CP_WAIT1(); } else { CP_WAIT0(); }
        __syncthreads();
        if (k + 2 < 32) load_chunk(k + 2);

        const uint32_t sA = sdata + (k % 3) * STAGE_BYTES;
        const uint32_t sB = sA + 16384;
        #pragma unroll
        for (int ks = 0; ks < 4; ks++) {
            uint32_t a[4][4], bb[4][2];
            const uint32_t cA = (((ks * 2 + hiA) ^ x7) << 4);
            const uint32_t cB = (((ks * 2 + hiB) ^ x7) << 4);
            #pragma unroll
            for (int mi = 0; mi < 4; mi++) LDSM4(a[mi], sA + rA[mi] + cA);
            #pragma unroll
            for (int np = 0; np < 2; np++) {
                uint32_t r[4];
                LDSM4(r, sB + rB[np] + cB);
                bb[np*2+0][0] = r[0]; bb[np*2+0][1] = r[1];
                bb[np*2+1][0] = r[2]; bb[np*2+1][1] = r[3];
            }
            #pragma unroll
            for (int mi = 0; mi < 4; mi++)
                #pragma unroll
                for (int nj = 0; nj < 4; nj++)
                    mma16816(acc[mi][nj], a[mi], bb[nj]);
        }
    }

    // epilogue: write G[b][m][n]; mirror to G[b][n][m] for off-diagonal tiles
    float* Gb = g_G + (size_t)b * HD * HD;
    const int mrow = m0 + wm * 64 + (lane >> 2);
    const int cloc = n0 + wn * 32 + (lane & 3) * 2;
    #pragma unroll
    for (int mi = 0; mi < 4; mi++)
        #pragma unroll
        for (int nj = 0; nj < 4; nj++) {
            int r = mrow + mi * 16;
            int c = cloc + nj * 8;
            float v0 = acc[mi][nj][0], v1 = acc[mi][nj][1];
            float v2 = acc[mi][nj][2], v3 = acc[mi][nj][3];
            *reinterpret_cast<float2*>(Gb + (size_t)r * HD + c)       = make_float2(v0, v1);
            *reinterpret_cast<float2*>(Gb + (size_t)(r + 8) * HD + c) = make_float2(v2, v3);
            if (mt != nt) {
                Gb[(size_t)c * HD + r]           = v0;
                Gb[(size_t)(c + 1) * HD + r]     = v1;
                Gb[(size_t)c * HD + r + 8]       = v2;
                Gb[(size_t)(c + 1) * HD + r + 8] = v3;
            }
        }
}

// ---------------- fused cumsum + combine ----------------
__global__ void __launch_bounds__(1024) final_kernel(const float* __restrict__ Aa,
                                                     const float* __restrict__ Bp,
                                                     const float* __restrict__ Dp,
                                                     float* __restrict__ out) {
    __shared__ float sd[32][33];
    __shared__ float sr[32][33];
    __shared__ float sy[32][33];
    const int tx = threadIdx.x, ty = threadIdx.y;
    const int h0 = blockIdx.x * 32;
    const int b  = blockIdx.y;
    const int w    = ty;
    const int lane = tx;
    const float A1  = Aa[h0 + w];
    const float B1  = Bp[h0 + w];
    const float Dv  = Dp[0];
    const float uCv = g_uC  [b * HD + h0 + w];
    const float Cv  = g_Csum[b * HD + h0 + w];
    const size_t base = (size_t)b * LD * HD;
    float carry = 0.f;

    for (int lt = 0; lt < LD; lt += 32) {
        size_t off = base + (size_t)(lt + ty) * HD + h0 + tx;
        sd[ty][tx] = __bfloat162float(g_deltab[off]);
        sr[ty][tx] = __bfloat162float(g_resb[off]);
        __syncthreads();
        float dv = sd[lane][w];
        float v  = dv * B1;
        #pragma unroll
        for (int o = 1; o < 32; o <<= 1) {
            float nb = __shfl_up_sync(0xffffffffu, v, o);
            if (lane >= o) v += nb;
        }
        float dB = carry + v;
        carry += __shfl_sync(0xffffffffu, v, 31);
        float dA = expf(dv * A1) * B1;
        sy[lane][w] = dA * uCv + dB * Cv + sr[lane][w] * Dv;
        __syncthreads();
        out[off] = sy[ty][tx];
    }
}

// ---------------- launch ----------------
extern "C" void kernel_launch(void* const* d_in, const int* in_sizes, int n_in,
                              void* d_out, int out_size) {
    (void)in_sizes; (void)n_in; (void)out_size;
    const float* x  = (const float*)d_in[0];
    const float* Wp = (const float*)d_in[1];
    const float* A  = (const float*)d_in[2];
    const float* Bp = (const float*)d_in[3];
    const float* D  = (const float*)d_in[4];
    const float* Wd = (const float*)d_in[5];
    const float* bd = (const float*)d_in[6];
    float* out = (float*)d_out;

    cudaFuncSetAttribute(gemm_mma, cudaFuncAttributeMaxDynamicSharedMemorySize, GEMM_SMEM);
    cudaFuncSetAttribute(gram_mma, cudaFuncAttributeMaxDynamicSharedMemorySize, GEMM_SMEM);

    zero_kernel<<<16, 256>>>();
    convx_colsum_kernel<<<dim3(HD / 512, BATCH, LD / 64), 256>>>(x);
    csum_kernel<<<512, 256>>>(Wp);
    conv_w_kernel<<<1024, 256>>>(Wp, Wd);
    conv_w1t_kernel<<<dim3(32, 32), dim3(32, 8)>>>(Wp);
    gemm_mma<<<dim3(8, 8),  256, GEMM_SMEM>>>(bd, 1);    // W_eff = W_delta @ W1
    gram_mma<<<BATCH * 36, 256, GEMM_SMEM>>>();          // G_b = x_b^T x_b (triangular)
    gemm_mma<<<dim3(16, 64), 256, GEMM_SMEM>>>(bd, 0);   // main GEMM (delta + residual)
    uc_matvec_kernel<<<512, 256>>>(Wp);
    final_kernel<<<dim3(HD / 32, BATCH), dim3(32, 32)>>>(A, Bp, D, out);
}

// round 9
// speedup vs baseline: 4.8102x; 1.1265x over previous
#include <cuda_runtime.h>
#include <cuda_bf16.h>
#include <cstdint>
#include <math.h>

#define HD   1024
#define LD   2048
#define BATCH 4
#define M_TOTAL 8192

// ---------------- scratch (no allocations allowed) ----------------
__device__ __align__(16) __nv_bfloat16 g_xb [(size_t)M_TOTAL * HD];
__device__ __align__(16) __nv_bfloat16 g_xT [(size_t)HD * M_TOTAL];      // x transposed: [h][b*L+l]
__device__ __align__(16) __nv_bfloat16 g_Wpb[(size_t)2048 * HD];         // [0,1024)=W_eff, [1024,2048)=W_res
__device__ __align__(16) __nv_bfloat16 g_W1T[(size_t)HD * HD];
__device__ __align__(16) __nv_bfloat16 g_Wdb[(size_t)HD * HD];
__device__ __align__(16) __nv_bfloat16 g_resb [(size_t)M_TOTAL * HD];
__device__ __align__(16) __nv_bfloat16 g_deltab[(size_t)M_TOTAL * HD];
__device__ __align__(16) float g_G[(size_t)BATCH * HD * HD];             // Gram matrices (symmetric, stored full)
__device__ float g_uC  [BATCH * HD];
__device__ float g_Csum[BATCH * HD];
__device__ float g_s   [BATCH * HD];

// ---------------- helpers ----------------
__device__ __forceinline__ uint32_t smem_u32(const void* p) {
    uint32_t a;
    asm("{ .reg .u64 t; cvta.to.shared.u64 t, %1; cvt.u32.u64 %0, t; }" : "=r"(a) : "l"(p));
    return a;
}
__device__ __forceinline__ void cp16(uint32_t s, const void* g) {
    asm volatile("cp.async.cg.shared.global [%0], [%1], 16;" :: "r"(s), "l"(g));
}
#define CP_COMMIT() asm volatile("cp.async.commit_group;" ::: "memory")
#define CP_WAIT1()  asm volatile("cp.async.wait_group 1;" ::: "memory")
#define CP_WAIT0()  asm volatile("cp.async.wait_group 0;" ::: "memory")

#define LDSM4(r, addr) \
    asm volatile("ldmatrix.sync.aligned.m8n8.x4.shared.b16 {%0,%1,%2,%3}, [%4];" \
        : "=r"((r)[0]), "=r"((r)[1]), "=r"((r)[2]), "=r"((r)[3]) : "r"(addr))

__device__ __forceinline__ void mma16816(float* c, const uint32_t* a, const uint32_t* b) {
    asm volatile(
        "mma.sync.aligned.m16n8k16.row.col.f32.bf16.bf16.f32 "
        "{%0,%1,%2,%3}, {%4,%5,%6,%7}, {%8,%9}, {%0,%1,%2,%3};"
        : "+f"(c[0]), "+f"(c[1]), "+f"(c[2]), "+f"(c[3])
        : "r"(a[0]), "r"(a[1]), "r"(a[2]), "r"(a[3]), "r"(b[0]), "r"(b[1]));
}
__device__ __forceinline__ uint32_t pack_bf2(float a, float b) {
    __nv_bfloat162 h = __floats2bfloat162_rn(a, b);
    return *reinterpret_cast<uint32_t*>(&h);
}

// ---------------- small kernels ----------------
__global__ void __launch_bounds__(256) zero_kernel() {
    int i = blockIdx.x * 256 + threadIdx.x;
    if (i < BATCH * HD) g_s[i] = 0.f;
}

// Fused: x -> bf16 (row-major AND transposed) + fp32 column sums. x read once.
__global__ void __launch_bounds__(256) convx_colsum_kernel(const float* __restrict__ x) {
    const int h  = (blockIdx.x * 256 + threadIdx.x) * 2;
    const int b  = blockIdx.y;
    const int l0 = blockIdx.z * 64;
    const float* p = x + ((size_t)b * LD + l0) * HD + h;
    __nv_bfloat16* q  = g_xb + ((size_t)b * LD + l0) * HD + h;
    __nv_bfloat16* t0 = g_xT + (size_t)h * M_TOTAL + b * LD + l0;
    __nv_bfloat16* t1 = t0 + M_TOTAL;
    float s0 = 0.f, s1 = 0.f;
    #pragma unroll
    for (int g = 0; g < 8; g++) {
        uint4 r0, r1;
        uint16_t* a0 = reinterpret_cast<uint16_t*>(&r0);
        uint16_t* a1 = reinterpret_cast<uint16_t*>(&r1);
        #pragma unroll
        for (int i = 0; i < 8; i++) {
            int l = g * 8 + i;
            float2 v = *reinterpret_cast<const float2*>(p + (size_t)l * HD);
            s0 += v.x; s1 += v.y;
            uint32_t pk = pack_bf2(v.x, v.y);
            *reinterpret_cast<uint32_t*>(q + (size_t)l * HD) = pk;
            a0[i] = (uint16_t)(pk & 0xffffu);
            a1[i] = (uint16_t)(pk >> 16);
        }
        *reinterpret_cast<uint4*>(t0 + g * 8) = r0;
        *reinterpret_cast<uint4*>(t1 + g * 8) = r1;
    }
    atomicAdd(&g_s[b * HD + h],     s0);
    atomicAdd(&g_s[b * HD + h + 1], s1);
}

// Merged exact-fp32 matvecs: Csum[b,h] = <W_C[h,:], g_s[b,:]>, uC[b,h] = <W_C[h,:], G_b[h,:]>
__global__ void __launch_bounds__(256) matvec_kernel(const float* __restrict__ Wp) {
    int gw   = blockIdx.x * 8 + (threadIdx.x >> 5);
    int lane = threadIdx.x & 31;
    int b = gw >> 10;
    int h = gw & (HD - 1);
    const float* w = Wp + (size_t)(2 * HD + h) * HD;
    const float* s = g_s + b * HD;
    const float* g = g_G + (size_t)b * HD * HD + (size_t)h * HD;
    float a1 = 0.f, a2 = 0.f;
    for (int k = lane; k < HD; k += 32) {
        float wv = w[k];
        a1 += wv * s[k];
        a2 += wv * g[k];
    }
    #pragma unroll
    for (int off = 16; off; off >>= 1) {
        a1 += __shfl_down_sync(0xffffffffu, a1, off);
        a2 += __shfl_down_sync(0xffffffffu, a2, off);
    }
    if (lane == 0) { g_Csum[gw] = a1; g_uC[gw] = a2; }
}

// Weight conversion: rows [0,1024): W_res (Wp rows 3072+) -> g_Wpb[1024..2048);
//                    rows [1024,2048): W_delta -> g_Wdb.
__global__ void __launch_bounds__(256) conv_w_kernel(const float* __restrict__ Wp,
                                                     const float* __restrict__ Wd) {
    int gid = blockIdx.x * 256 + threadIdx.x;
    int row = gid >> 7;
    int c   = (gid & 127) * 8;
    const float* in;
    __nv_bfloat16* outp;
    if (row < 1024) {
        in   = Wp + (size_t)(row + 3072) * HD + c;
        outp = g_Wpb + (size_t)(row + 1024) * HD + c;
    } else {
        in   = Wd + (size_t)(row - 1024) * HD + c;
        outp = g_Wdb + (size_t)(row - 1024) * HD + c;
    }
    float4 a = *reinterpret_cast<const float4*>(in);
    float4 b = *reinterpret_cast<const float4*>(in + 4);
    uint4 o;
    o.x = pack_bf2(a.x, a.y); o.y = pack_bf2(a.z, a.w);
    o.z = pack_bf2(b.x, b.y); o.w = pack_bf2(b.z, b.w);
    *reinterpret_cast<uint4*>(outp) = o;
}

// W1 = W_proj rows [0,1024): transpose-convert -> g_W1T[n][j] = bf16(W1[j][n])
__global__ void __launch_bounds__(256) conv_w1t_kernel(const float* __restrict__ Wp) {
    __shared__ float tile[32][33];
    const int tx = threadIdx.x, ty = threadIdx.y;       // 32 x 8
    const int bx = blockIdx.x * 32, by = blockIdx.y * 32;
    #pragma unroll
    for (int p = 0; p < 4; p++)
        tile[ty + p * 8][tx] = Wp[(size_t)(by + ty + p * 8) * HD + bx + tx];
    __syncthreads();
    #pragma unroll
    for (int p = 0; p < 4; p++) {
        int r = ty + p * 8;
        g_W1T[(size_t)(bx + r) * HD + by + tx] = __float2bfloat16(tile[tx][r]);
    }
}

// ---------------- bf16 mma.sync GEMM core constants ----------------
constexpr int STAGE_BYTES = 32768;
constexpr int GEMM_SMEM   = 1024 + 3 * STAGE_BYTES;

// Main / W_eff GEMM. mode 0: A=g_xb, B=g_Wpb (N=2048): n0<1024 delta; else residual.
//                    mode 1: A=g_Wdb, B=g_W1T -> W_eff into g_Wpb[0,1024).
__global__ void __launch_bounds__(256, 2)
gemm_mma(const float* __restrict__ bd, int mode) {
    extern __shared__ char smem[];
    const uint32_t sdata = smem_u32(smem) + 1024;

    const int tid  = threadIdx.x;
    const int lane = tid & 31;
    const int warp = tid >> 5;
    const int wm   = warp >> 2;
    const int wn   = warp & 3;
    const int m0   = blockIdx.y * 128;
    const int n0   = blockIdx.x * 128;

    const __nv_bfloat16* Ab = mode ? g_Wdb : g_xb;
    const __nv_bfloat16* Bb = mode ? g_W1T : g_Wpb;

    const uint32_t x7  = lane & 7;
    const uint32_t hiA = lane >> 4;
    const uint32_t hiB = (lane >> 3) & 1;
    uint32_t rA[4], rB[2];
    #pragma unroll
    for (int mi = 0; mi < 4; mi++)
        rA[mi] = (uint32_t)(wm * 64 + mi * 16 + (lane & 15)) * 128;
    #pragma unroll
    for (int np = 0; np < 2; np++)
        rB[np] = (uint32_t)(wn * 32 + np * 16 + (lane & 7) + ((lane & 16) >> 1)) * 128;

    float acc[4][4][4];
    #pragma unroll
    for (int i = 0; i < 4; i++)
        #pragma unroll
        for (int j = 0; j < 4; j++)
            #pragma unroll
            for (int e = 0; e < 4; e++) acc[i][j][e] = 0.f;

    auto load_chunk = [&](int c) {
        const uint32_t sA = sdata + (c % 3) * STAGE_BYTES;
        const uint32_t sB = sA + 16384;
        const __nv_bfloat16* gA = Ab + (size_t)m0 * HD + c * 64;
        const __nv_bfloat16* gB = Bb + (size_t)n0 * HD + c * 64;
        #pragma unroll
        for (int it = 0; it < 4; it++) {
            int seg = tid + it * 256;
            int row = seg >> 3;
            int c16 = seg & 7;
            uint32_t off = row * 128 + ((c16 ^ (row & 7)) << 4);
            cp16(sA + off, gA + (size_t)row * HD + c16 * 8);
        }
        #pragma unroll
        for (int it = 0; it < 4; it++) {
            int seg = tid + it * 256;
            int row = seg >> 3;
            int c16 = seg & 7;
            uint32_t off = row * 128 + ((c16 ^ (row & 7)) << 4);
            cp16(sB + off, gB + (size_t)row * HD + c16 * 8);
        }
        CP_COMMIT();
    };

    load_chunk(0); load_chunk(1);

    #pragma unroll 1
    for (int k = 0; k < 16; k++) {
        if (k < 14) { CP_WAIT1(); } else { CP_WAIT0(); }
        __syncthreads();
        if (k + 2 < 16) load_chunk(k + 2);

        const uint32_t sA = sdata + (k % 3) * STAGE_BYTES;
        const uint32_t sB = sA + 16384;
        #pragma unroll
        for (int ks = 0; ks < 4; ks++) {
            uint32_t a[4][4], b[4][2];
            const uint32_t cA = (((ks * 2 + hiA) ^ x7) << 4);
            const uint32_t cB = (((ks * 2 + hiB) ^ x7) << 4);
            #pragma unroll
            for (int mi = 0; mi < 4; mi++) LDSM4(a[mi], sA + rA[mi] + cA);
            #pragma unroll
            for (int np = 0; np < 2; np++) {
                uint32_t r[4];
                LDSM4(r, sB + rB[np] + cB);
                b[np*2+0][0] = r[0]; b[np*2+0][1] = r[1];
                b[np*2+1][0] = r[2]; b[np*2+1][1] = r[3];
            }
            #pragma unroll
            for (int mi = 0; mi < 4; mi++)
                #pragma unroll
                for (int nj = 0; nj < 4; nj++)
                    mma16816(acc[mi][nj], a[mi], b[nj]);
        }
    }

    // -------- epilogue (register-direct) --------
    const int mrow = m0 + wm * 64 + (lane >> 2);
    const int cloc = wn * 32 + (lane & 3) * 2;

    if (mode == 1) {                            // W_eff -> bf16 g_Wpb[0,1024)
        #pragma unroll
        for (int mi = 0; mi < 4; mi++)
            #pragma unroll
            for (int nj = 0; nj < 4; nj++) {
                int r = mrow + mi * 16;
                int c = n0 + cloc + nj * 8;
                *reinterpret_cast<uint32_t*>(g_Wpb + (size_t)r * HD + c) =
                    pack_bf2(acc[mi][nj][0], acc[mi][nj][1]);
                *reinterpret_cast<uint32_t*>(g_Wpb + (size_t)(r + 8) * HD + c) =
                    pack_bf2(acc[mi][nj][2], acc[mi][nj][3]);
            }
    } else if (n0 < 1024) {                     // delta = softplus(. + bd) -> bf16
        #pragma unroll
        for (int mi = 0; mi < 4; mi++)
            #pragma unroll
            for (int nj = 0; nj < 4; nj++) {
                int r = mrow + mi * 16;
                int c = n0 + cloc + nj * 8;
                float b0 = bd[c], b1 = bd[c + 1];
                float v0 = acc[mi][nj][0] + b0;
                float v1 = acc[mi][nj][1] + b1;
                float v2 = acc[mi][nj][2] + b0;
                float v3 = acc[mi][nj][3] + b1;
                v0 = (v0 > 20.f) ? v0 : log1pf(expf(v0));
                v1 = (v1 > 20.f) ? v1 : log1pf(expf(v1));
                v2 = (v2 > 20.f) ? v2 : log1pf(expf(v2));
                v3 = (v3 > 20.f) ? v3 : log1pf(expf(v3));
                *reinterpret_cast<uint32_t*>(g_deltab + (size_t)r * HD + c) = pack_bf2(v0, v1);
                *reinterpret_cast<uint32_t*>(g_deltab + (size_t)(r + 8) * HD + c) = pack_bf2(v2, v3);
            }
    } else {                                    // residual -> bf16
        const int cb = n0 - 1024;
        #pragma unroll
        for (int mi = 0; mi < 4; mi++)
            #pragma unroll
            for (int nj = 0; nj < 4; nj++) {
                int r = mrow + mi * 16;
                int c = cb + cloc + nj * 8;
                *reinterpret_cast<uint32_t*>(g_resb + (size_t)r * HD + c) =
                    pack_bf2(acc[mi][nj][0], acc[mi][nj][1]);
                *reinterpret_cast<uint32_t*>(g_resb + (size_t)(r + 8) * HD + c) =
                    pack_bf2(acc[mi][nj][2], acc[mi][nj][3]);
            }
    }
}

// ---------------- Gram GEMM: G_b = x_b^T x_b (upper-triangle tiles + mirror) ----------------
__global__ void __launch_bounds__(256, 2)
gram_mma() {
    extern __shared__ char smem[];
    const uint32_t sdata = smem_u32(smem) + 1024;

    const int tid  = threadIdx.x;
    const int lane = tid & 31;
    const int warp = tid >> 5;
    const int wm   = warp >> 2;
    const int wn   = warp & 3;

    int idx = blockIdx.x % 36;
    const int b = blockIdx.x / 36;
    int mt = 0;
    while (idx >= 8 - mt) { idx -= 8 - mt; mt++; }
    const int nt = mt + idx;
    const int m0 = mt * 128;
    const int n0 = nt * 128;
    const size_t kbase = (size_t)b * LD;

    const uint32_t x7  = lane & 7;
    const uint32_t hiA = lane >> 4;
    const uint32_t hiB = (lane >> 3) & 1;
    uint32_t rA[4], rB[2];
    #pragma unroll
    for (int mi = 0; mi < 4; mi++)
        rA[mi] = (uint32_t)(wm * 64 + mi * 16 + (lane & 15)) * 128;
    #pragma unroll
    for (int np = 0; np < 2; np++)
        rB[np] = (uint32_t)(wn * 32 + np * 16 + (lane & 7) + ((lane & 16) >> 1)) * 128;

    float acc[4][4][4];
    #pragma unroll
    for (int i = 0; i < 4; i++)
        #pragma unroll
        for (int j = 0; j < 4; j++)
            #pragma unroll
            for (int e = 0; e < 4; e++) acc[i][j][e] = 0.f;

    auto load_chunk = [&](int c) {
        const uint32_t sA = sdata + (c % 3) * STAGE_BYTES;
        const uint32_t sB = sA + 16384;
        const __nv_bfloat16* gA = g_xT + (size_t)m0 * M_TOTAL + kbase + c * 64;
        const __nv_bfloat16* gB = g_xT + (size_t)n0 * M_TOTAL + kbase + c * 64;
        #pragma unroll
        for (int it = 0; it < 4; it++) {
            int seg = tid + it * 256;
            int row = seg >> 3;
            int c16 = seg & 7;
            uint32_t off = row * 128 + ((c16 ^ (row & 7)) << 4);
            cp16(sA + off, gA + (size_t)row * M_TOTAL + c16 * 8);
        }
        #pragma unroll
        for (int it = 0; it < 4; it++) {
            int seg = tid + it * 256;
            int row = seg >> 3;
            int c16 = seg & 7;
            uint32_t off = row * 128 + ((c16 ^ (row & 7)) << 4);
            cp16(sB + off, gB + (size_t)row * M_TOTAL + c16 * 8);
        }
        CP_COMMIT();
    };

    load_chunk(0); load_chunk(1);

    #pragma unroll 1
    for (int k = 0; k < 32; k++) {
        if (k < 30) { CP_WAIT1(); } else { CP_WAIT0(); }
        __syncthreads();
        if (k + 2 < 32) load_chunk(k + 2);

        const uint32_t sA = sdata + (k % 3) * STAGE_BYTES;
        const uint32_t sB = sA + 16384;
        #pragma unroll
        for (int ks = 0; ks < 4; ks++) {
            uint32_t a[4][4], bb[4][2];
            const uint32_t cA = (((ks * 2 + hiA) ^ x7) << 4);
            const uint32_t cB = (((ks * 2 + hiB) ^ x7) << 4);
            #pragma unroll
            for (int mi = 0; mi < 4; mi++) LDSM4(a[mi], sA + rA[mi] + cA);
            #pragma unroll
            for (int np = 0; np < 2; np++) {
                uint32_t r[4];
                LDSM4(r, sB + rB[np] + cB);
                bb[np*2+0][0] = r[0]; bb[np*2+0][1] = r[1];
                bb[np*2+1][0] = r[2]; bb[np*2+1][1] = r[3];
            }
            #pragma unroll
            for (int mi = 0; mi < 4; mi++)
                #pragma unroll
                for (int nj = 0; nj < 4; nj++)
                    mma16816(acc[mi][nj], a[mi], bb[nj]);
        }
    }

    float* Gb = g_G + (size_t)b * HD * HD;
    const int mrow = m0 + wm * 64 + (lane >> 2);
    const int cloc = n0 + wn * 32 + (lane & 3) * 2;
    #pragma unroll
    for (int mi = 0; mi < 4; mi++)
        #pragma unroll
        for (int nj = 0; nj < 4; nj++) {
            int r = mrow + mi * 16;
            int c = cloc + nj * 8;
            float v0 = acc[mi][nj][0], v1 = acc[mi][nj][1];
            float v2 = acc[mi][nj][2], v3 = acc[mi][nj][3];
            *reinterpret_cast<float2*>(Gb + (size_t)r * HD + c)       = make_float2(v0, v1);
            *reinterpret_cast<float2*>(Gb + (size_t)(r + 8) * HD + c) = make_float2(v2, v3);
            if (mt != nt) {
                Gb[(size_t)c * HD + r]           = v0;
                Gb[(size_t)(c + 1) * HD + r]     = v1;
                Gb[(size_t)c * HD + r + 8]       = v2;
                Gb[(size_t)(c + 1) * HD + r + 8] = v3;
            }
        }
}

// ---------------- fused cumsum + combine ----------------
__global__ void __launch_bounds__(1024) final_kernel(const float* __restrict__ Aa,
                                                     const float* __restrict__ Bp,
                                                     const float* __restrict__ Dp,
                                                     float* __restrict__ out) {
    __shared__ float sd[32][33];
    __shared__ float sr[32][33];
    __shared__ float sy[32][33];
    const int tx = threadIdx.x, ty = threadIdx.y;
    const int h0 = blockIdx.x * 32;
    const int b  = blockIdx.y;
    const int w    = ty;
    const int lane = tx;
    const float A1  = Aa[h0 + w];
    const float B1  = Bp[h0 + w];
    const float Dv  = Dp[0];
    const float uCv = g_uC  [b * HD + h0 + w];
    const float Cv  = g_Csum[b * HD + h0 + w];
    const size_t base = (size_t)b * LD * HD;
    float carry = 0.f;

    for (int lt = 0; lt < LD; lt += 32) {
        size_t off = base + (size_t)(lt + ty) * HD + h0 + tx;
        sd[ty][tx] = __bfloat162float(g_deltab[off]);
        sr[ty][tx] = __bfloat162float(g_resb[off]);
        __syncthreads();
        float dv = sd[lane][w];
        float v  = dv * B1;
        #pragma unroll
        for (int o = 1; o < 32; o <<= 1) {
            float nb = __shfl_up_sync(0xffffffffu, v, o);
            if (lane >= o) v += nb;
        }
        float dB = carry + v;
        carry += __shfl_sync(0xffffffffu, v, 31);
        float dA = expf(dv * A1) * B1;
        sy[lane][w] = dA * uCv + dB * Cv + sr[lane][w] * Dv;
        __syncthreads();
        out[off] = sy[ty][tx];
    }
}

// ---------------- launch (multi-stream fork/join, capture-safe) ----------------
extern "C" void kernel_launch(void* const* d_in, const int* in_sizes, int n_in,
                              void* d_out, int out_size) {
    (void)in_sizes; (void)n_in; (void)out_size;
    const float* x  = (const float*)d_in[0];
    const float* Wp = (const float*)d_in[1];
    const float* A  = (const float*)d_in[2];
    const float* Bp = (const float*)d_in[3];
    const float* D  = (const float*)d_in[4];
    const float* Wd = (const float*)d_in[5];
    const float* bd = (const float*)d_in[6];
    float* out = (float*)d_out;

    cudaFuncSetAttribute(gemm_mma, cudaFuncAttributeMaxDynamicSharedMemorySize, GEMM_SMEM);
    cudaFuncSetAttribute(gram_mma, cudaFuncAttributeMaxDynamicSharedMemorySize, GEMM_SMEM);

    // fork a worker stream off the (possibly capturing) default stream
    cudaStream_t sB;
    cudaStreamCreateWithFlags(&sB, cudaStreamNonBlocking);
    cudaEvent_t evRoot, evX, evB;
    cudaEventCreateWithFlags(&evRoot, cudaEventDisableTiming);
    cudaEventCreateWithFlags(&evX,    cudaEventDisableTiming);
    cudaEventCreateWithFlags(&evB,    cudaEventDisableTiming);

    cudaEventRecord(evRoot, 0);
    cudaStreamWaitEvent(sB, evRoot, 0);

    // stream B: weight prologue + W_eff (independent of x)
    conv_w_kernel<<<1024, 256, 0, sB>>>(Wp, Wd);
    conv_w1t_kernel<<<dim3(32, 32), dim3(32, 8), 0, sB>>>(Wp);
    gemm_mma<<<dim3(8, 8), 256, GEMM_SMEM, sB>>>(bd, 1);        // W_eff = W_delta @ W1

    // default stream: x conversion chain
    zero_kernel<<<16, 256>>>();
    convx_colsum_kernel<<<dim3(HD / 512, BATCH, LD / 64), 256>>>(x);
    cudaEventRecord(evX, 0);

    // stream B: main GEMM needs g_xb (evX) + g_Wpb (sB order)
    cudaStreamWaitEvent(sB, evX, 0);
    gemm_mma<<<dim3(16, 64), 256, GEMM_SMEM, sB>>>(bd, 0);      // delta + residual

    // default stream (concurrent with main GEMM): gram + matvecs
    gram_mma<<<BATCH * 36, 256, GEMM_SMEM>>>();                 // G_b = x_b^T x_b
    matvec_kernel<<<512, 256>>>(Wp);                            // Csum + uC

    // join and finish
    cudaEventRecord(evB, sB);
    cudaStreamWaitEvent(0, evB, 0);
    final_kernel<<<dim3(HD / 32, BATCH), dim3(32, 32)>>>(A, Bp, D, out);
    // streams/events intentionally not destroyed (capture may still be active;
    // kernel_launch is invoked only a handful of times, so the leak is bounded)
}